// round 5
// baseline (speedup 1.0000x reference)
#include <cuda_runtime.h>
#include <math.h>

// ---------------------------------------------------------------------------
// HungarianContrastiveLoss
//   outputs:  (256,16,1024) fp32 -> O  (4096 x 1024)
//   positive: (256,16,1024) fp32 -> P  (4096 x 1024)
//   negative: (256,16,1024) fp32 -> Ng (4096 x 1024)
//   sim = (O/0.05) @ [P;Ng]^T   (4096 x 8192)
//   loss = mean_r( LSE(sim[r,:]) - sim[r, hungarian_col(r)] )
//
// Decomposition:
//   K1 gemm_lse:   streaming GEMM; per (row, 128-col tile) emit (max, sum exp)
//   K2 diag:       recompute the 256 diagonal 16x16 blocks (O_b . P_b^T)
//   K3 hungarian:  serial JV per batch (1 thread / batch) -> matched values
//   K4 finalize:   combine partial LSEs, mean(LSE - matched)
// ---------------------------------------------------------------------------

#define NROWS 4096
#define NCOLS 8192
#define DIM   1024
#define NTILE 64            // NCOLS / 128
#define SCALE 20.0f         // 1 / 0.05

// scratch (device globals: allocation-free rule)
__device__ float g_pmax[NTILE * NROWS];
__device__ float g_psum[NTILE * NROWS];
__device__ float g_blocks[256 * 256];   // 256 problems of 16x16 (already scaled)
__device__ float g_matched[NROWS];

// ---------------------------------------------------------------------------
// Kernel 1: streaming GEMM + per-tile logsumexp partials.
// BM=BN=128, BK=16, 256 threads, 8x8 microtile, register prefetch.
// ---------------------------------------------------------------------------
__global__ __launch_bounds__(256) void gemm_lse_kernel(
    const float* __restrict__ O, const float* __restrict__ P,
    const float* __restrict__ Ng)
{
    const int bn = blockIdx.x;   // 0..63 (column tile)
    const int bm = blockIdx.y;   // 0..31 (row tile)
    const int tid = threadIdx.x;
    const int tx = tid & 15;     // column group
    const int ty = tid >> 4;     // row group

    __shared__ float As[16][128];   // As[k][m]
    __shared__ float Bs[16][128];   // Bs[k][n]

    const float* Abase = O + (size_t)bm * 128 * DIM;
    const float* Bbase = (bn < 32) ? (P + (size_t)bn * 128 * DIM)
                                   : (Ng + (size_t)(bn - 32) * 128 * DIM);

    float acc[8][8];
#pragma unroll
    for (int i = 0; i < 8; i++)
#pragma unroll
        for (int j = 0; j < 8; j++) acc[i][j] = 0.f;

    // per-thread gmem load slots: 2 float4 per matrix per K-tile
    int lrow[2], lcol[2];
#pragma unroll
    for (int q = 0; q < 2; q++) {
        int idx = q * 256 + tid;         // 0..511
        lrow[q] = idx >> 2;              // 0..127
        lcol[q] = (idx & 3) << 2;        // 0,4,8,12
    }

    float4 ra[2], rb[2];
#pragma unroll
    for (int q = 0; q < 2; q++) {
        ra[q] = *(const float4*)(Abase + (size_t)lrow[q] * DIM + lcol[q]);
        rb[q] = *(const float4*)(Bbase + (size_t)lrow[q] * DIM + lcol[q]);
    }

    for (int kt = 0; kt < DIM / 16; kt++) {
        // commit prefetched regs to smem (transposed)
#pragma unroll
        for (int q = 0; q < 2; q++) {
            int r = lrow[q], c = lcol[q];
            As[c + 0][r] = ra[q].x; As[c + 1][r] = ra[q].y;
            As[c + 2][r] = ra[q].z; As[c + 3][r] = ra[q].w;
            Bs[c + 0][r] = rb[q].x; Bs[c + 1][r] = rb[q].y;
            Bs[c + 2][r] = rb[q].z; Bs[c + 3][r] = rb[q].w;
        }
        __syncthreads();

        if (kt + 1 < DIM / 16) {
            int koff = (kt + 1) * 16;
#pragma unroll
            for (int q = 0; q < 2; q++) {
                ra[q] = *(const float4*)(Abase + (size_t)lrow[q] * DIM + koff + lcol[q]);
                rb[q] = *(const float4*)(Bbase + (size_t)lrow[q] * DIM + koff + lcol[q]);
            }
        }

#pragma unroll
        for (int k = 0; k < 16; k++) {
            float a[8], b[8];
            *(float4*)(a)     = *(const float4*)&As[k][ty * 8];
            *(float4*)(a + 4) = *(const float4*)&As[k][ty * 8 + 4];
            *(float4*)(b)     = *(const float4*)&Bs[k][tx * 8];
            *(float4*)(b + 4) = *(const float4*)&Bs[k][tx * 8 + 4];
#pragma unroll
            for (int i = 0; i < 8; i++)
#pragma unroll
                for (int j = 0; j < 8; j++) acc[i][j] += a[i] * b[j];
        }
        __syncthreads();
    }

    // epilogue: per-row (within this 128-col tile) max & sum(exp)
#pragma unroll
    for (int i = 0; i < 8; i++) {
        int row = bm * 128 + ty * 8 + i;
        float v[8];
        float m = -1e30f;
#pragma unroll
        for (int j = 0; j < 8; j++) { v[j] = acc[i][j] * SCALE; m = fmaxf(m, v[j]); }
        // reduce max over the 16 column-threads (16-wide shuffle segments)
#pragma unroll
        for (int off = 8; off; off >>= 1)
            m = fmaxf(m, __shfl_xor_sync(0xffffffffu, m, off, 16));
        float s = 0.f;
#pragma unroll
        for (int j = 0; j < 8; j++) s += __expf(v[j] - m);
#pragma unroll
        for (int off = 8; off; off >>= 1)
            s += __shfl_xor_sync(0xffffffffu, s, off, 16);
        if (tx == 0) {
            g_pmax[bn * NROWS + row] = m;
            g_psum[bn * NROWS + row] = s;
        }
    }
}

// ---------------------------------------------------------------------------
// Kernel 2: diagonal 16x16 blocks  block[b][i][j] = SCALE * <O[b*16+i], P[b*16+j]>
// ---------------------------------------------------------------------------
__global__ __launch_bounds__(256) void diag_blocks_kernel(
    const float* __restrict__ O, const float* __restrict__ P)
{
    const int b = blockIdx.x;
    __shared__ float so[16][257];
    __shared__ float sp[16][257];
    const int i = threadIdx.x >> 4;
    const int j = threadIdx.x & 15;

    float acc = 0.f;
    for (int k0 = 0; k0 < DIM; k0 += 256) {
        for (int t = threadIdx.x; t < 16 * 256; t += 256) {
            int r = t >> 8, c = t & 255;
            so[r][c] = O[(size_t)(b * 16 + r) * DIM + k0 + c];
            sp[r][c] = P[(size_t)(b * 16 + r) * DIM + k0 + c];
        }
        __syncthreads();
#pragma unroll 8
        for (int k = 0; k < 256; k++) acc += so[i][k] * sp[j][k];
        __syncthreads();
    }
    g_blocks[b * 256 + threadIdx.x] = acc * SCALE;
}

// ---------------------------------------------------------------------------
// Kernel 3: Hungarian (Jonker-Volgenant, minimize -block).
// SERIAL: one thread per batch. No intra-kernel synchronization whatsoever,
// so no possibility of divergence-induced deadlock. n=16 -> ~40k ops/thread.
// ---------------------------------------------------------------------------
__global__ __launch_bounds__(32) void hungarian_kernel()
{
    const int b = blockIdx.x * 32 + threadIdx.x;
    if (b >= 256) return;

    // local (per-thread) working set
    float C[16 * 16];
    float u[17], v[17], minv[17];
    int   p[17], way[17];
    bool  used[17];

    const float* blk = &g_blocks[b * 256];
#pragma unroll 4
    for (int t = 0; t < 256; t++) C[t] = -blk[t];

    for (int j = 0; j <= 16; j++) { u[j] = 0.f; v[j] = 0.f; p[j] = 0; }

    for (int i = 1; i <= 16; i++) {
        p[0] = i;
        int j0 = 0;
        for (int j = 0; j <= 16; j++) { minv[j] = 1e30f; used[j] = false; }

        // shortest augmenting path (bounded: each pass marks a new column used)
        for (int guard = 0; guard <= 16; guard++) {
            used[j0] = true;
            const int i0 = p[j0];
            float delta = 1e30f;
            int j1 = -1;
            for (int j = 1; j <= 16; j++) {
                if (!used[j]) {
                    float cur = C[(i0 - 1) * 16 + (j - 1)] - u[i0] - v[j];
                    if (cur < minv[j]) { minv[j] = cur; way[j] = j0; }
                    if (minv[j] < delta) { delta = minv[j]; j1 = j; }
                }
            }
            for (int j = 0; j <= 16; j++) {
                if (used[j]) { u[p[j]] += delta; v[j] -= delta; }
                else         { minv[j] -= delta; }
            }
            j0 = j1;
            if (p[j0] == 0) break;
        }
        // augment along the alternating path
        while (j0) {
            int j1 = way[j0];
            p[j0] = p[j1];
            j0 = j1;
        }
    }

    // p[j] = row (1-based) matched to column j-1; emit matched raw sim value
    for (int j = 1; j <= 16; j++) {
        int row = p[j] - 1;
        g_matched[b * 16 + row] = blk[row * 16 + (j - 1)];
    }
}

// ---------------------------------------------------------------------------
// Kernel 4: combine LSE partials, subtract matched, deterministic mean.
// ---------------------------------------------------------------------------
__global__ __launch_bounds__(1024) void finalize_kernel(float* __restrict__ out)
{
    __shared__ float red[1024];
    float local = 0.f;
    for (int r = threadIdx.x; r < NROWS; r += 1024) {
        float M = -1e30f;
#pragma unroll 8
        for (int t = 0; t < NTILE; t++) M = fmaxf(M, g_pmax[t * NROWS + r]);
        float S = 0.f;
#pragma unroll 8
        for (int t = 0; t < NTILE; t++)
            S += g_psum[t * NROWS + r] * __expf(g_pmax[t * NROWS + r] - M);
        local += (M + logf(S)) - g_matched[r];
    }
    red[threadIdx.x] = local;
    __syncthreads();
    for (int s = 512; s; s >>= 1) {
        if (threadIdx.x < s) red[threadIdx.x] += red[threadIdx.x + s];
        __syncthreads();
    }
    if (threadIdx.x == 0) out[0] = red[0] * (1.0f / (float)NROWS);
}

// ---------------------------------------------------------------------------
extern "C" void kernel_launch(void* const* d_in, const int* in_sizes, int n_in,
                              void* d_out, int out_size)
{
    const float* O  = (const float*)d_in[0];
    const float* P  = (const float*)d_in[1];
    const float* Ng = (const float*)d_in[2];
    float* out = (float*)d_out;

    gemm_lse_kernel<<<dim3(NTILE, NROWS / 128), 256>>>(O, P, Ng);
    diag_blocks_kernel<<<256, 256>>>(O, P);
    hungarian_kernel<<<8, 32>>>();
    finalize_kernel<<<1, 1024>>>(out);
}

// round 11
// speedup vs baseline: 3.9221x; 3.9221x over previous
#include <cuda_runtime.h>
#include <cuda_bf16.h>
#include <math.h>
#include <stdint.h>

// ---------------------------------------------------------------------------
// HungarianContrastiveLoss on GB300 (sm_103 base-ISA tensor cores)
//   sim = (O/0.05) @ [P;Ng]^T   (4096 x 8192, K=1024)
//   loss = mean_r( LSE(sim[r,:]) - sim[r, hungarian_col(r)] )
//
//   K0 convert:    fp32 -> bf16 copies of O and E=[P;Ng]
//   K1 gemm_bf16:  mma.sync m16n8k16 bf16 GEMM (128x128 tiles, cp.async
//                  double buffer) + streaming base-2 LSE partials
//   K2 diag:       exact fp32 diagonal 16x16 blocks (assignment + matched)
//   K3 hungarian:  serial JV per batch (1 thread / batch)
//   K4a/K4b:       deterministic parallel finalize
// ---------------------------------------------------------------------------

#define NROWS  4096
#define NCOLSS 8192
#define DIM    1024
#define NTILE  64            // 8192 / 128 column tiles
#define SCALE  20.0f
#define C1     28.853900817779268f   // 20 * log2(e)
#define LN2f   0.6931471805599453f

#define BM 128
#define BN 128
#define BK 32
#define PITCH 40             // halves per SMEM row (80 B: 5 mod 8 -> no LDSM conflicts)

// device-global scratch (allocation-free rule)
__device__ __nv_bfloat16 g_Obf[NROWS * DIM];
__device__ __nv_bfloat16 g_Ebf[NCOLSS * DIM];   // rows 0..4095 = P, 4096..8191 = Ng
__device__ float g_pmax[NTILE * NROWS];
__device__ float g_psum[NTILE * NROWS];
__device__ float g_blocks[256 * 256];
__device__ float g_matched[NROWS];
__device__ float g_partial[32];

// ---------------------------------------------------------------------------
// helpers
// ---------------------------------------------------------------------------
__device__ __forceinline__ uint32_t smem_u32(const void* p) {
    uint32_t a;
    asm("{ .reg .u64 t; cvta.to.shared.u64 t, %1; cvt.u32.u64 %0, t; }" : "=r"(a) : "l"(p));
    return a;
}
__device__ __forceinline__ void cp16(uint32_t dst, const void* src) {
    asm volatile("cp.async.cg.shared.global [%0], [%1], 16;" :: "r"(dst), "l"(src));
}
__device__ __forceinline__ float ex2f(float x) {
    float y; asm("ex2.approx.f32 %0, %1;" : "=f"(y) : "f"(x)); return y;
}
__device__ __forceinline__ float lg2f(float x) {
    float y; asm("lg2.approx.f32 %0, %1;" : "=f"(y) : "f"(x)); return y;
}
#define LDSM4(R0, R1, R2, R3, ADDR)                                             \
    asm volatile("ldmatrix.sync.aligned.m8n8.x4.shared.b16 {%0,%1,%2,%3}, [%4];"\
                 : "=r"(R0), "=r"(R1), "=r"(R2), "=r"(R3) : "r"(ADDR))

#define MMA_BF16(D, A, B0, B1)                                                  \
    asm volatile("mma.sync.aligned.m16n8k16.row.col.f32.bf16.bf16.f32 "         \
                 "{%0,%1,%2,%3}, {%4,%5,%6,%7}, {%8,%9}, {%0,%1,%2,%3};"        \
                 : "+f"((D)[0]), "+f"((D)[1]), "+f"((D)[2]), "+f"((D)[3])       \
                 : "r"((A)[0]), "r"((A)[1]), "r"((A)[2]), "r"((A)[3]),          \
                   "r"(B0), "r"(B1))

// ---------------------------------------------------------------------------
// Kernel 0: fp32 -> bf16 conversion of all three tensors.
// ---------------------------------------------------------------------------
__global__ __launch_bounds__(256) void convert_kernel(
    const float4* __restrict__ O, const float4* __restrict__ P,
    const float4* __restrict__ Ng)
{
    const int N4 = NROWS * DIM / 4;   // per tensor
    uint32_t* ob = (uint32_t*)g_Obf;
    uint32_t* eb = (uint32_t*)g_Ebf;
    for (int i = blockIdx.x * 256 + threadIdx.x; i < 3 * N4; i += gridDim.x * 256) {
        float4 v; uint32_t* dst;
        if (i < N4)           { v = O[i];           dst = ob + (size_t)i * 2; }
        else if (i < 2 * N4)  { int j = i - N4;     v = P[j];  dst = eb + (size_t)j * 2; }
        else                  { int j = i - 2 * N4; v = Ng[j]; dst = eb + (size_t)(N4 + j) * 2; }
        __nv_bfloat162 lo = __float22bfloat162_rn(make_float2(v.x, v.y));
        __nv_bfloat162 hi = __float22bfloat162_rn(make_float2(v.z, v.w));
        dst[0] = *(uint32_t*)&lo;
        dst[1] = *(uint32_t*)&hi;
    }
}

// ---------------------------------------------------------------------------
// Kernel 1: bf16 mma.sync GEMM + streaming base-2 LSE partials.
// grid (64, 32), 256 threads = 8 warps (4 m x 2 n), warp tile 32x64.
// ---------------------------------------------------------------------------
__device__ __forceinline__ void issue_chunk(
    const __nv_bfloat16* __restrict__ Ab, const __nv_bfloat16* __restrict__ Bb,
    uint32_t sA, uint32_t sB, int chunk, int tid)
{
    const int gk = chunk * BK;
#pragma unroll
    for (int it = 0; it < 2; it++) {
        int idx = it * 256 + tid;          // 0..511
        int r = idx >> 2;                  // row 0..127
        int q = idx & 3;                   // 8-half quarter
        cp16(sA + r * (PITCH * 2) + q * 16, Ab + (size_t)r * DIM + gk + q * 8);
        cp16(sB + r * (PITCH * 2) + q * 16, Bb + (size_t)r * DIM + gk + q * 8);
    }
}

__global__ __launch_bounds__(256) void gemm_bf16_kernel()
{
    __shared__ __align__(16) __nv_bfloat16 As[2][BM * PITCH];
    __shared__ __align__(16) __nv_bfloat16 Bs[2][BN * PITCH];

    const int tid  = threadIdx.x;
    const int lane = tid & 31;
    const int wid  = tid >> 5;
    const int wm   = wid & 3;      // 0..3 (m)
    const int wn   = wid >> 2;     // 0..1 (n)
    const int bn = blockIdx.x, bm = blockIdx.y;

    const __nv_bfloat16* Ab = g_Obf + (size_t)bm * BM * DIM;
    const __nv_bfloat16* Bb = g_Ebf + (size_t)bn * BN * DIM;

    const uint32_t sA0 = smem_u32(&As[0][0]);
    const uint32_t sB0 = smem_u32(&Bs[0][0]);
    const uint32_t stageA = BM * PITCH * 2;   // bytes
    const uint32_t stageB = BN * PITCH * 2;

    // per-lane ldmatrix address components (bytes)
    // A: row = wm*32 + mt*16 + (lane&7) + ((lane>>3)&1)*8 ; col = kb + (lane>>4)*8
    // B: row = wn*64 + nq*16 + (lane&7) + (lane>>4)*8     ; col = kb + ((lane>>3)&1)*8
    const uint32_t aRow = (uint32_t)(wm * 32 + (lane & 7) + ((lane >> 3) & 1) * 8);
    const uint32_t aCol = (uint32_t)((lane >> 4) * 8);
    const uint32_t bRow = (uint32_t)(wn * 64 + (lane & 7) + (lane >> 4) * 8);
    const uint32_t bCol = (uint32_t)(((lane >> 3) & 1) * 8);

    float acc[2][8][4];
#pragma unroll
    for (int mt = 0; mt < 2; mt++)
#pragma unroll
        for (int nt = 0; nt < 8; nt++)
#pragma unroll
            for (int k = 0; k < 4; k++) acc[mt][nt][k] = 0.f;

    issue_chunk(Ab, Bb, sA0, sB0, 0, tid);
    asm volatile("cp.async.commit_group;" ::: "memory");

    for (int c = 0; c < DIM / BK; c++) {
        const int st = c & 1;
        if (c < DIM / BK - 1) {
            issue_chunk(Ab, Bb, sA0 + (st ^ 1) * stageA, sB0 + (st ^ 1) * stageB,
                        c + 1, tid);
            asm volatile("cp.async.commit_group;" ::: "memory");
            asm volatile("cp.async.wait_group 1;" ::: "memory");
        } else {
            asm volatile("cp.async.wait_group 0;" ::: "memory");
        }
        __syncthreads();

        const uint32_t baseA = sA0 + st * stageA;
        const uint32_t baseB = sB0 + st * stageB;
#pragma unroll
        for (int ks = 0; ks < 2; ks++) {
            const uint32_t kb = (uint32_t)(ks * 16);
            uint32_t a[2][4];
#pragma unroll
            for (int mt = 0; mt < 2; mt++) {
                uint32_t addr = baseA + (aRow + mt * 16) * (PITCH * 2) + (kb + aCol) * 2;
                LDSM4(a[mt][0], a[mt][1], a[mt][2], a[mt][3], addr);
            }
            uint32_t b[4][4];
#pragma unroll
            for (int nq = 0; nq < 4; nq++) {
                uint32_t addr = baseB + (bRow + nq * 16) * (PITCH * 2) + (kb + bCol) * 2;
                LDSM4(b[nq][0], b[nq][1], b[nq][2], b[nq][3], addr);
            }
#pragma unroll
            for (int mt = 0; mt < 2; mt++)
#pragma unroll
                for (int nt = 0; nt < 8; nt++)
                    MMA_BF16(acc[mt][nt], a[mt], b[nt >> 1][(nt & 1) * 2],
                             b[nt >> 1][(nt & 1) * 2 + 1]);
        }
        __syncthreads();
    }

    // ---- epilogue: per-row base-2 LSE over this 128-col tile ----
    // d0,d1 -> row (lane>>2), cols (lane&3)*2 {+1}; d2,d3 -> row+8.
    float2* part = (float2*)&As[0][0];    // reuse: 2*128 float2 = 2 KB

#pragma unroll
    for (int mt = 0; mt < 2; mt++) {
#pragma unroll
        for (int hf = 0; hf < 2; hf++) {
            float m = -1e30f;
            float e[16];
#pragma unroll
            for (int nt = 0; nt < 8; nt++) {
                e[nt * 2 + 0] = acc[mt][nt][hf * 2 + 0] * C1;
                e[nt * 2 + 1] = acc[mt][nt][hf * 2 + 1] * C1;
                m = fmaxf(m, fmaxf(e[nt * 2], e[nt * 2 + 1]));
            }
            float s = 0.f;
#pragma unroll
            for (int k = 0; k < 16; k++) s += ex2f(e[k] - m);
            // combine across the 4 lanes sharing this row (lane&3 varies)
#pragma unroll
            for (int off = 1; off <= 2; off <<= 1) {
                float om = __shfl_xor_sync(0xffffffffu, m, off);
                float os = __shfl_xor_sync(0xffffffffu, s, off);
                float nm = fmaxf(m, om);
                s = s * ex2f(m - nm) + os * ex2f(om - nm);
                m = nm;
            }
            if ((lane & 3) == 0) {
                int row = wm * 32 + mt * 16 + hf * 8 + (lane >> 2);
                part[wn * 128 + row] = make_float2(m, s);
            }
        }
    }
    __syncthreads();
    if (tid < 128) {
        float2 p0 = part[tid];
        float2 p1 = part[128 + tid];
        float M = fmaxf(p0.x, p1.x);
        float S = p0.y * ex2f(p0.x - M) + p1.y * ex2f(p1.x - M);
        const int row = bm * BM + tid;
        g_pmax[bn * NROWS + row] = M;
        g_psum[bn * NROWS + row] = S;
    }
}

// ---------------------------------------------------------------------------
// Kernel 2: exact fp32 diagonal 16x16 blocks (scaled).
// ---------------------------------------------------------------------------
__global__ __launch_bounds__(256) void diag_blocks_kernel(
    const float* __restrict__ O, const float* __restrict__ P)
{
    const int b = blockIdx.x;
    __shared__ float so[16][257];
    __shared__ float sp[16][257];
    const int i = threadIdx.x >> 4;
    const int j = threadIdx.x & 15;

    float acc = 0.f;
    for (int k0 = 0; k0 < DIM; k0 += 256) {
        for (int t = threadIdx.x; t < 16 * 256; t += 256) {
            int r = t >> 8, c = t & 255;
            so[r][c] = O[(size_t)(b * 16 + r) * DIM + k0 + c];
            sp[r][c] = P[(size_t)(b * 16 + r) * DIM + k0 + c];
        }
        __syncthreads();
#pragma unroll 8
        for (int k = 0; k < 256; k++) acc += so[i][k] * sp[j][k];
        __syncthreads();
    }
    g_blocks[b * 256 + threadIdx.x] = acc * SCALE;
}

// ---------------------------------------------------------------------------
// Kernel 3: Hungarian (Jonker-Volgenant), one serial thread per batch.
// ---------------------------------------------------------------------------
__global__ __launch_bounds__(32) void hungarian_kernel()
{
    const int b = blockIdx.x * 32 + threadIdx.x;
    if (b >= 256) return;

    float C[16 * 16];
    float u[17], v[17], minv[17];
    int   p[17], way[17];
    bool  used[17];

    const float* blk = &g_blocks[b * 256];
#pragma unroll 4
    for (int t = 0; t < 256; t++) C[t] = -blk[t];
    for (int j = 0; j <= 16; j++) { u[j] = 0.f; v[j] = 0.f; p[j] = 0; }

    for (int i = 1; i <= 16; i++) {
        p[0] = i;
        int j0 = 0;
        for (int j = 0; j <= 16; j++) { minv[j] = 1e30f; used[j] = false; }
        for (int guard = 0; guard <= 16; guard++) {
            used[j0] = true;
            const int i0 = p[j0];
            float delta = 1e30f;
            int j1 = -1;
            for (int j = 1; j <= 16; j++) {
                if (!used[j]) {
                    float cur = C[(i0 - 1) * 16 + (j - 1)] - u[i0] - v[j];
                    if (cur < minv[j]) { minv[j] = cur; way[j] = j0; }
                    if (minv[j] < delta) { delta = minv[j]; j1 = j; }
                }
            }
            for (int j = 0; j <= 16; j++) {
                if (used[j]) { u[p[j]] += delta; v[j] -= delta; }
                else         { minv[j] -= delta; }
            }
            j0 = j1;
            if (p[j0] == 0) break;
        }
        while (j0) { int j1 = way[j0]; p[j0] = p[j1]; j0 = j1; }
    }
    for (int j = 1; j <= 16; j++) {
        int row = p[j] - 1;
        g_matched[b * 16 + row] = blk[row * 16 + (j - 1)];
    }
}

// ---------------------------------------------------------------------------
// Kernel 4a: per-row loss (32 CTAs); 4b: deterministic final sum.
// LSE_nat(r) = ln2 * (M2 + log2(sum_t s_t * 2^(m_t - M2)))
// ---------------------------------------------------------------------------
__global__ __launch_bounds__(128) void finalize_rows_kernel()
{
    __shared__ float red[128];
    const int row = blockIdx.x * 128 + threadIdx.x;
    float M = -1e30f;
#pragma unroll 8
    for (int t = 0; t < NTILE; t++) M = fmaxf(M, g_pmax[t * NROWS + row]);
    float S = 0.f;
#pragma unroll 8
    for (int t = 0; t < NTILE; t++)
        S += g_psum[t * NROWS + row] * ex2f(g_pmax[t * NROWS + row] - M);
    red[threadIdx.x] = LN2f * (M + lg2f(S)) - g_matched[row];
    __syncthreads();
    for (int s = 64; s; s >>= 1) {
        if (threadIdx.x < s) red[threadIdx.x] += red[threadIdx.x + s];
        __syncthreads();
    }
    if (threadIdx.x == 0) g_partial[blockIdx.x] = red[0];
}

__global__ __launch_bounds__(32) void finalize_sum_kernel(float* __restrict__ out)
{
    float v = g_partial[threadIdx.x];
#pragma unroll
    for (int off = 16; off; off >>= 1) v += __shfl_xor_sync(0xffffffffu, v, off);
    if (threadIdx.x == 0) out[0] = v * (1.0f / (float)NROWS);
}

// ---------------------------------------------------------------------------
extern "C" void kernel_launch(void* const* d_in, const int* in_sizes, int n_in,
                              void* d_out, int out_size)
{
    const float* O  = (const float*)d_in[0];
    const float* P  = (const float*)d_in[1];
    const float* Ng = (const float*)d_in[2];
    float* out = (float*)d_out;

    convert_kernel<<<2048, 256>>>((const float4*)O, (const float4*)P,
                                  (const float4*)Ng);
    gemm_bf16_kernel<<<dim3(NTILE, NROWS / BM), 256>>>();
    diag_blocks_kernel<<<256, 256>>>(O, P);
    hungarian_kernel<<<8, 32>>>();
    finalize_rows_kernel<<<NROWS / 128, 128>>>();
    finalize_sum_kernel<<<1, 32>>>(out);
}

// round 12
// speedup vs baseline: 5.7942x; 1.4773x over previous
#include <cuda_runtime.h>
#include <cuda_bf16.h>
#include <math.h>
#include <stdint.h>

// ---------------------------------------------------------------------------
// HungarianContrastiveLoss on GB300 (sm_103 base-ISA tensor cores)
//   sim = (O/0.05) @ [P;Ng]^T   (4096 x 8192, K=1024)
//   loss = mean_r( LSE(sim[r,:]) - sim[r, hungarian_col(r)] )
//
//   K0 convert:    fp32 -> bf16 copies of O and E=[P;Ng]
//   K1 gemm_bf16:  mma.sync m16n8k16 bf16 GEMM (128x128 tiles, cp.async
//                  double buffer) + streaming base-2 LSE partials
//   K2 diag:       exact fp32 diagonal 16x16 blocks (assignment + matched)
//   K3 hungarian:  warp-cooperative JV, one warp per batch, 256 warps
//   K4a/K4b:       deterministic parallel finalize
// ---------------------------------------------------------------------------

#define NROWS  4096
#define NCOLSS 8192
#define DIM    1024
#define NTILE  64            // 8192 / 128 column tiles
#define SCALE  20.0f
#define C1     28.853900817779268f   // 20 * log2(e)
#define LN2f   0.6931471805599453f

#define BM 128
#define BN 128
#define BK 32
#define PITCH 40             // halves per SMEM row (80 B: 5 mod 8 -> no LDSM conflicts)

// device-global scratch (allocation-free rule)
__device__ __nv_bfloat16 g_Obf[NROWS * DIM];
__device__ __nv_bfloat16 g_Ebf[NCOLSS * DIM];   // rows 0..4095 = P, 4096..8191 = Ng
__device__ float g_pmax[NTILE * NROWS];
__device__ float g_psum[NTILE * NROWS];
__device__ float g_blocks[256 * 256];
__device__ float g_matched[NROWS];
__device__ float g_partial[32];

// ---------------------------------------------------------------------------
// helpers
// ---------------------------------------------------------------------------
__device__ __forceinline__ uint32_t smem_u32(const void* p) {
    uint32_t a;
    asm("{ .reg .u64 t; cvta.to.shared.u64 t, %1; cvt.u32.u64 %0, t; }" : "=r"(a) : "l"(p));
    return a;
}
__device__ __forceinline__ void cp16(uint32_t dst, const void* src) {
    asm volatile("cp.async.cg.shared.global [%0], [%1], 16;" :: "r"(dst), "l"(src));
}
__device__ __forceinline__ float ex2f(float x) {
    float y; asm("ex2.approx.f32 %0, %1;" : "=f"(y) : "f"(x)); return y;
}
__device__ __forceinline__ float lg2f(float x) {
    float y; asm("lg2.approx.f32 %0, %1;" : "=f"(y) : "f"(x)); return y;
}
#define LDSM4(R0, R1, R2, R3, ADDR)                                             \
    asm volatile("ldmatrix.sync.aligned.m8n8.x4.shared.b16 {%0,%1,%2,%3}, [%4];"\
                 : "=r"(R0), "=r"(R1), "=r"(R2), "=r"(R3) : "r"(ADDR))

#define MMA_BF16(D, A, B0, B1)                                                  \
    asm volatile("mma.sync.aligned.m16n8k16.row.col.f32.bf16.bf16.f32 "         \
                 "{%0,%1,%2,%3}, {%4,%5,%6,%7}, {%8,%9}, {%0,%1,%2,%3};"        \
                 : "+f"((D)[0]), "+f"((D)[1]), "+f"((D)[2]), "+f"((D)[3])       \
                 : "r"((A)[0]), "r"((A)[1]), "r"((A)[2]), "r"((A)[3]),          \
                   "r"(B0), "r"(B1))

// ---------------------------------------------------------------------------
// Kernel 0: fp32 -> bf16 conversion of all three tensors.
// ---------------------------------------------------------------------------
__global__ __launch_bounds__(256) void convert_kernel(
    const float4* __restrict__ O, const float4* __restrict__ P,
    const float4* __restrict__ Ng)
{
    const int N4 = NROWS * DIM / 4;   // per tensor
    uint32_t* ob = (uint32_t*)g_Obf;
    uint32_t* eb = (uint32_t*)g_Ebf;
    for (int i = blockIdx.x * 256 + threadIdx.x; i < 3 * N4; i += gridDim.x * 256) {
        float4 v; uint32_t* dst;
        if (i < N4)           { v = O[i];           dst = ob + (size_t)i * 2; }
        else if (i < 2 * N4)  { int j = i - N4;     v = P[j];  dst = eb + (size_t)j * 2; }
        else                  { int j = i - 2 * N4; v = Ng[j]; dst = eb + (size_t)(N4 + j) * 2; }
        __nv_bfloat162 lo = __float22bfloat162_rn(make_float2(v.x, v.y));
        __nv_bfloat162 hi = __float22bfloat162_rn(make_float2(v.z, v.w));
        dst[0] = *(uint32_t*)&lo;
        dst[1] = *(uint32_t*)&hi;
    }
}

// ---------------------------------------------------------------------------
// Kernel 1: bf16 mma.sync GEMM + streaming base-2 LSE partials.
// grid (64, 32), 256 threads = 8 warps (4 m x 2 n), warp tile 32x64.
// ---------------------------------------------------------------------------
__device__ __forceinline__ void issue_chunk(
    const __nv_bfloat16* __restrict__ Ab, const __nv_bfloat16* __restrict__ Bb,
    uint32_t sA, uint32_t sB, int chunk, int tid)
{
    const int gk = chunk * BK;
#pragma unroll
    for (int it = 0; it < 2; it++) {
        int idx = it * 256 + tid;          // 0..511
        int r = idx >> 2;                  // row 0..127
        int q = idx & 3;                   // 8-half quarter
        cp16(sA + r * (PITCH * 2) + q * 16, Ab + (size_t)r * DIM + gk + q * 8);
        cp16(sB + r * (PITCH * 2) + q * 16, Bb + (size_t)r * DIM + gk + q * 8);
    }
}

__global__ __launch_bounds__(256) void gemm_bf16_kernel()
{
    __shared__ __align__(16) __nv_bfloat16 As[2][BM * PITCH];
    __shared__ __align__(16) __nv_bfloat16 Bs[2][BN * PITCH];

    const int tid  = threadIdx.x;
    const int lane = tid & 31;
    const int wid  = tid >> 5;
    const int wm   = wid & 3;      // 0..3 (m)
    const int wn   = wid >> 2;     // 0..1 (n)
    const int bn = blockIdx.x, bm = blockIdx.y;

    const __nv_bfloat16* Ab = g_Obf + (size_t)bm * BM * DIM;
    const __nv_bfloat16* Bb = g_Ebf + (size_t)bn * BN * DIM;

    const uint32_t sA0 = smem_u32(&As[0][0]);
    const uint32_t sB0 = smem_u32(&Bs[0][0]);
    const uint32_t stageA = BM * PITCH * 2;   // bytes
    const uint32_t stageB = BN * PITCH * 2;

    const uint32_t aRow = (uint32_t)(wm * 32 + (lane & 7) + ((lane >> 3) & 1) * 8);
    const uint32_t aCol = (uint32_t)((lane >> 4) * 8);
    const uint32_t bRow = (uint32_t)(wn * 64 + (lane & 7) + (lane >> 4) * 8);
    const uint32_t bCol = (uint32_t)(((lane >> 3) & 1) * 8);

    float acc[2][8][4];
#pragma unroll
    for (int mt = 0; mt < 2; mt++)
#pragma unroll
        for (int nt = 0; nt < 8; nt++)
#pragma unroll
            for (int k = 0; k < 4; k++) acc[mt][nt][k] = 0.f;

    issue_chunk(Ab, Bb, sA0, sB0, 0, tid);
    asm volatile("cp.async.commit_group;" ::: "memory");

    for (int c = 0; c < DIM / BK; c++) {
        const int st = c & 1;
        if (c < DIM / BK - 1) {
            issue_chunk(Ab, Bb, sA0 + (st ^ 1) * stageA, sB0 + (st ^ 1) * stageB,
                        c + 1, tid);
            asm volatile("cp.async.commit_group;" ::: "memory");
            asm volatile("cp.async.wait_group 1;" ::: "memory");
        } else {
            asm volatile("cp.async.wait_group 0;" ::: "memory");
        }
        __syncthreads();

        const uint32_t baseA = sA0 + st * stageA;
        const uint32_t baseB = sB0 + st * stageB;
#pragma unroll
        for (int ks = 0; ks < 2; ks++) {
            const uint32_t kb = (uint32_t)(ks * 16);
            uint32_t a[2][4];
#pragma unroll
            for (int mt = 0; mt < 2; mt++) {
                uint32_t addr = baseA + (aRow + mt * 16) * (PITCH * 2) + (kb + aCol) * 2;
                LDSM4(a[mt][0], a[mt][1], a[mt][2], a[mt][3], addr);
            }
            uint32_t b[4][4];
#pragma unroll
            for (int nq = 0; nq < 4; nq++) {
                uint32_t addr = baseB + (bRow + nq * 16) * (PITCH * 2) + (kb + bCol) * 2;
                LDSM4(b[nq][0], b[nq][1], b[nq][2], b[nq][3], addr);
            }
#pragma unroll
            for (int mt = 0; mt < 2; mt++)
#pragma unroll
                for (int nt = 0; nt < 8; nt++)
                    MMA_BF16(acc[mt][nt], a[mt], b[nt >> 1][(nt & 1) * 2],
                             b[nt >> 1][(nt & 1) * 2 + 1]);
        }
        __syncthreads();
    }

    // ---- epilogue: per-row base-2 LSE over this 128-col tile ----
    float2* part = (float2*)&As[0][0];    // reuse: 2*128 float2 = 2 KB

#pragma unroll
    for (int mt = 0; mt < 2; mt++) {
#pragma unroll
        for (int hf = 0; hf < 2; hf++) {
            float m = -1e30f;
            float e[16];
#pragma unroll
            for (int nt = 0; nt < 8; nt++) {
                e[nt * 2 + 0] = acc[mt][nt][hf * 2 + 0] * C1;
                e[nt * 2 + 1] = acc[mt][nt][hf * 2 + 1] * C1;
                m = fmaxf(m, fmaxf(e[nt * 2], e[nt * 2 + 1]));
            }
            float s = 0.f;
#pragma unroll
            for (int k = 0; k < 16; k++) s += ex2f(e[k] - m);
#pragma unroll
            for (int off = 1; off <= 2; off <<= 1) {
                float om = __shfl_xor_sync(0xffffffffu, m, off);
                float os = __shfl_xor_sync(0xffffffffu, s, off);
                float nm = fmaxf(m, om);
                s = s * ex2f(m - nm) + os * ex2f(om - nm);
                m = nm;
            }
            if ((lane & 3) == 0) {
                int row = wm * 32 + mt * 16 + hf * 8 + (lane >> 2);
                part[wn * 128 + row] = make_float2(m, s);
            }
        }
    }
    __syncthreads();
    if (tid < 128) {
        float2 p0 = part[tid];
        float2 p1 = part[128 + tid];
        float M = fmaxf(p0.x, p1.x);
        float S = p0.y * ex2f(p0.x - M) + p1.y * ex2f(p1.x - M);
        const int row = bm * BM + tid;
        g_pmax[bn * NROWS + row] = M;
        g_psum[bn * NROWS + row] = S;
    }
}

// ---------------------------------------------------------------------------
// Kernel 2: exact fp32 diagonal 16x16 blocks (scaled).
// ---------------------------------------------------------------------------
__global__ __launch_bounds__(256) void diag_blocks_kernel(
    const float* __restrict__ O, const float* __restrict__ P)
{
    const int b = blockIdx.x;
    __shared__ float so[16][257];
    __shared__ float sp[16][257];
    const int i = threadIdx.x >> 4;
    const int j = threadIdx.x & 15;

    float acc = 0.f;
    for (int k0 = 0; k0 < DIM; k0 += 256) {
        for (int t = threadIdx.x; t < 16 * 256; t += 256) {
            int r = t >> 8, c = t & 255;
            so[r][c] = O[(size_t)(b * 16 + r) * DIM + k0 + c];
            sp[r][c] = P[(size_t)(b * 16 + r) * DIM + k0 + c];
        }
        __syncthreads();
#pragma unroll 8
        for (int k = 0; k < 256; k++) acc += so[i][k] * sp[j][k];
        __syncthreads();
    }
    g_blocks[b * 256 + threadIdx.x] = acc * SCALE;
}

// ---------------------------------------------------------------------------
// Kernel 3: Hungarian (Jonker-Volgenant), ONE WARP PER BATCH.
// Lane j-1 owns column j: minv/way/v live in registers; only u[17], p[17],
// way[17], C[256] in SMEM. The argmin butterfly carries (value,index) with an
// index tie-break, so (delta, j1) is bit-identical on every lane ->
// j0 and the loop exit are warp-uniform -> all __syncwarp convergent.
// ---------------------------------------------------------------------------
#define HWARPS 4
__global__ __launch_bounds__(32 * HWARPS) void hungarian_kernel()
{
    __shared__ float sC[HWARPS][256];
    __shared__ float su[HWARPS][17];
    __shared__ int   sp[HWARPS][17];
    __shared__ int   sway[HWARPS][17];

    const int w    = threadIdx.x >> 5;
    const int lane = threadIdx.x & 31;
    const int b    = blockIdx.x * HWARPS + w;

    float* C   = sC[w];
    float* u   = su[w];
    int*   p   = sp[w];
    int*   way = sway[w];

    const float* blk = &g_blocks[b * 256];
    for (int t = lane; t < 256; t += 32) C[t] = -blk[t];
    if (lane < 17) { u[lane] = 0.f; p[lane] = 0; }
    float v = 0.f;            // lane<16: potential of column (lane+1)
    __syncwarp();

    for (int i = 1; i <= 16; i++) {
        if (lane == 0) p[0] = i;
        float minv = 1e30f;
        int   wayr = 0;
        unsigned used = 0u;   // replicated bitmask, identical in all lanes
        int j0 = 0;
        __syncwarp();

        for (int guard = 0; guard <= 16; guard++) {
            used |= (1u << j0);
            const int i0  = p[j0];
            const float ui0 = u[i0];

            float d = 1e30f;
            int   jm = 63;
            if (lane < 16) {
                const int j = lane + 1;
                if (!((used >> j) & 1u)) {
                    float cur = C[(i0 - 1) * 16 + lane] - ui0 - v;
                    if (cur < minv) { minv = cur; wayr = j0; }
                    d = minv; jm = j;
                }
            }
            // deterministic (min, argmin) butterfly: index tie-break
#pragma unroll
            for (int off = 16; off; off >>= 1) {
                float od = __shfl_xor_sync(0xffffffffu, d, off);
                int   oj = __shfl_xor_sync(0xffffffffu, jm, off);
                if (od < d || (od == d && oj < jm)) { d = od; jm = oj; }
            }
            // dual updates
            if (lane < 16) {
                const int j = lane + 1;
                if ((used >> j) & 1u) { v -= d; u[p[j]] += d; }
                else                  { minv -= d; }
            } else if (lane == 16) {
                u[p[0]] += d;      // j = 0 (virtual column) is always used
            }
            __syncwarp();
            j0 = jm;
            if (p[j0] == 0) break;
        }

        // publish way registers, then augment (serial, lane 0)
        if (lane < 16) way[lane + 1] = wayr;
        __syncwarp();
        if (lane == 0) {
            int jj = j0;
            while (jj) { int j1 = way[jj]; p[jj] = p[j1]; jj = j1; }
        }
        __syncwarp();
    }

    if (lane < 16) {
        const int row = p[lane + 1] - 1;   // row matched to column `lane`
        g_matched[b * 16 + row] = blk[row * 16 + lane];
    }
}

// ---------------------------------------------------------------------------
// Kernel 4a: per-row loss (32 CTAs); 4b: deterministic final sum.
// LSE_nat(r) = ln2 * (M2 + log2(sum_t s_t * 2^(m_t - M2)))
// ---------------------------------------------------------------------------
__global__ __launch_bounds__(128) void finalize_rows_kernel()
{
    __shared__ float red[128];
    const int row = blockIdx.x * 128 + threadIdx.x;
    float M = -1e30f;
#pragma unroll 8
    for (int t = 0; t < NTILE; t++) M = fmaxf(M, g_pmax[t * NROWS + row]);
    float S = 0.f;
#pragma unroll 8
    for (int t = 0; t < NTILE; t++)
        S += g_psum[t * NROWS + row] * ex2f(g_pmax[t * NROWS + row] - M);
    red[threadIdx.x] = LN2f * (M + lg2f(S)) - g_matched[row];
    __syncthreads();
    for (int s = 64; s; s >>= 1) {
        if (threadIdx.x < s) red[threadIdx.x] += red[threadIdx.x + s];
        __syncthreads();
    }
    if (threadIdx.x == 0) g_partial[blockIdx.x] = red[0];
}

__global__ __launch_bounds__(32) void finalize_sum_kernel(float* __restrict__ out)
{
    float v = g_partial[threadIdx.x];
#pragma unroll
    for (int off = 16; off; off >>= 1) v += __shfl_xor_sync(0xffffffffu, v, off);
    if (threadIdx.x == 0) out[0] = v * (1.0f / (float)NROWS);
}

// ---------------------------------------------------------------------------
extern "C" void kernel_launch(void* const* d_in, const int* in_sizes, int n_in,
                              void* d_out, int out_size)
{
    const float* O  = (const float*)d_in[0];
    const float* P  = (const float*)d_in[1];
    const float* Ng = (const float*)d_in[2];
    float* out = (float*)d_out;

    convert_kernel<<<2048, 256>>>((const float4*)O, (const float4*)P,
                                  (const float4*)Ng);
    gemm_bf16_kernel<<<dim3(NTILE, NROWS / BM), 256>>>();
    diag_blocks_kernel<<<256, 256>>>(O, P);
    hungarian_kernel<<<256 / HWARPS, 32 * HWARPS>>>();
    finalize_rows_kernel<<<NROWS / 128, 128>>>();
    finalize_sum_kernel<<<1, 32>>>(out);
}

// round 13
// speedup vs baseline: 6.1169x; 1.0557x over previous
#include <cuda_runtime.h>
#include <cuda_bf16.h>
#include <math.h>
#include <stdint.h>

// ---------------------------------------------------------------------------
// HungarianContrastiveLoss on GB300 (sm_103 base-ISA tensor cores)
//   sim = (O/0.05) @ [P;Ng]^T   (4096 x 8192, K=1024)
//   loss = mean_r( LSE(sim[r,:]) - sim[r, hungarian_col(r)] )
//
//   K0 convert: fp32 -> bf16 copies of O and E=[P;Ng]
//   K1 fused:   bids 0..2047  : bf16 mma.sync GEMM (128x128 tile, 3-stage
//                               cp.async) + streaming base-2 LSE partials
//               bids 2048..2303: exact fp32 diag 16x16 block + warp JV
//                               (redux.sync argmin) -> g_matched
//   K2 finalize: per-row loss + fused deterministic mean (last-block sum)
// ---------------------------------------------------------------------------

#define NROWS  4096
#define NCOLSS 8192
#define DIM    1024
#define NTILE  64            // 8192 / 128 column tiles
#define SCALE  20.0f
#define C1     28.853900817779268f   // 20 * log2(e)
#define LN2f   0.6931471805599453f

#define BM 128
#define BN 128
#define BK 32
#define PITCH 40             // halves per SMEM row (80 B: 5 mod 8 -> no LDSM conflicts)

#define STAGE_A  (BM * PITCH * 2)          // 10240 B
#define STAGE_B  (BN * PITCH * 2)          // 10240 B
#define STAGE_SZ (STAGE_A + STAGE_B)       // 20480 B
#define NSTAGES  3
#define SMEM_DYN (NSTAGES * STAGE_SZ)      // 61440 B

#define GEMM_CTAS (NTILE * (NROWS / BM))   // 2048
#define TOTAL_CTAS (GEMM_CTAS + 256)

// device-global scratch (allocation-free rule)
__device__ __nv_bfloat16 g_Obf[NROWS * DIM];
__device__ __nv_bfloat16 g_Ebf[NCOLSS * DIM];   // rows 0..4095 = P, 4096..8191 = Ng
__device__ float g_pmax[NTILE * NROWS];
__device__ float g_psum[NTILE * NROWS];
__device__ float g_matched[NROWS];
__device__ float g_partial[32];
__device__ unsigned g_done;                     // zero-init; reset by last block

// ---------------------------------------------------------------------------
// helpers
// ---------------------------------------------------------------------------
__device__ __forceinline__ uint32_t smem_u32(const void* p) {
    uint32_t a;
    asm("{ .reg .u64 t; cvta.to.shared.u64 t, %1; cvt.u32.u64 %0, t; }" : "=r"(a) : "l"(p));
    return a;
}
__device__ __forceinline__ void cp16(uint32_t dst, const void* src) {
    asm volatile("cp.async.cg.shared.global [%0], [%1], 16;" :: "r"(dst), "l"(src));
}
__device__ __forceinline__ float ex2f(float x) {
    float y; asm("ex2.approx.f32 %0, %1;" : "=f"(y) : "f"(x)); return y;
}
__device__ __forceinline__ float lg2f(float x) {
    float y; asm("lg2.approx.f32 %0, %1;" : "=f"(y) : "f"(x)); return y;
}
// order-preserving float <-> uint (for redux.sync.min on floats)
__device__ __forceinline__ unsigned ordf(float f) {
    unsigned u = __float_as_uint(f);
    return (u & 0x80000000u) ? ~u : (u | 0x80000000u);
}
__device__ __forceinline__ float unordf(unsigned u) {
    u = (u & 0x80000000u) ? (u & 0x7FFFFFFFu) : ~u;
    return __uint_as_float(u);
}
#define LDSM4(R0, R1, R2, R3, ADDR)                                             \
    asm volatile("ldmatrix.sync.aligned.m8n8.x4.shared.b16 {%0,%1,%2,%3}, [%4];"\
                 : "=r"(R0), "=r"(R1), "=r"(R2), "=r"(R3) : "r"(ADDR))

#define MMA_BF16(D, A, B0, B1)                                                  \
    asm volatile("mma.sync.aligned.m16n8k16.row.col.f32.bf16.bf16.f32 "         \
                 "{%0,%1,%2,%3}, {%4,%5,%6,%7}, {%8,%9}, {%0,%1,%2,%3};"        \
                 : "+f"((D)[0]), "+f"((D)[1]), "+f"((D)[2]), "+f"((D)[3])       \
                 : "r"((A)[0]), "r"((A)[1]), "r"((A)[2]), "r"((A)[3]),          \
                   "r"(B0), "r"(B1))

// ---------------------------------------------------------------------------
// Kernel 0: fp32 -> bf16 conversion of all three tensors.
// ---------------------------------------------------------------------------
__global__ __launch_bounds__(256) void convert_kernel(
    const float4* __restrict__ O, const float4* __restrict__ P,
    const float4* __restrict__ Ng)
{
    const int N4 = NROWS * DIM / 4;   // per tensor
    uint32_t* ob = (uint32_t*)g_Obf;
    uint32_t* eb = (uint32_t*)g_Ebf;
    for (int i = blockIdx.x * 256 + threadIdx.x; i < 3 * N4; i += gridDim.x * 256) {
        float4 v; uint32_t* dst;
        if (i < N4)           { v = O[i];           dst = ob + (size_t)i * 2; }
        else if (i < 2 * N4)  { int j = i - N4;     v = P[j];  dst = eb + (size_t)j * 2; }
        else                  { int j = i - 2 * N4; v = Ng[j]; dst = eb + (size_t)(N4 + j) * 2; }
        __nv_bfloat162 lo = __float22bfloat162_rn(make_float2(v.x, v.y));
        __nv_bfloat162 hi = __float22bfloat162_rn(make_float2(v.z, v.w));
        dst[0] = *(uint32_t*)&lo;
        dst[1] = *(uint32_t*)&hi;
    }
}

// ---------------------------------------------------------------------------
// GEMM tile path (bids 0..2047)
// ---------------------------------------------------------------------------
__device__ __forceinline__ void issue_chunk(
    const __nv_bfloat16* __restrict__ Ab, const __nv_bfloat16* __restrict__ Bb,
    uint32_t sA, uint32_t sB, int chunk, int tid)
{
    const int gk = chunk * BK;
#pragma unroll
    for (int it = 0; it < 2; it++) {
        int idx = it * 256 + tid;          // 0..511
        int r = idx >> 2;                  // row 0..127
        int q = idx & 3;                   // 8-half quarter
        cp16(sA + r * (PITCH * 2) + q * 16, Ab + (size_t)r * DIM + gk + q * 8);
        cp16(sB + r * (PITCH * 2) + q * 16, Bb + (size_t)r * DIM + gk + q * 8);
    }
}

__device__ void gemm_path(uint8_t* smem, int bid)
{
    const int tid  = threadIdx.x;
    const int lane = tid & 31;
    const int wid  = tid >> 5;
    const int wm   = wid & 3;      // 0..3 (m)
    const int wn   = wid >> 2;     // 0..1 (n)
    const int bn = bid & (NTILE - 1);
    const int bm = bid >> 6;

    const __nv_bfloat16* Ab = g_Obf + (size_t)bm * BM * DIM;
    const __nv_bfloat16* Bb = g_Ebf + (size_t)bn * BN * DIM;

    const uint32_t s0 = smem_u32(smem);

    const uint32_t aRow = (uint32_t)(wm * 32 + (lane & 7) + ((lane >> 3) & 1) * 8);
    const uint32_t aCol = (uint32_t)((lane >> 4) * 8);
    const uint32_t bRow = (uint32_t)(wn * 64 + (lane & 7) + (lane >> 4) * 8);
    const uint32_t bCol = (uint32_t)(((lane >> 3) & 1) * 8);

    float acc[2][8][4];
#pragma unroll
    for (int mt = 0; mt < 2; mt++)
#pragma unroll
        for (int nt = 0; nt < 8; nt++)
#pragma unroll
            for (int k = 0; k < 4; k++) acc[mt][nt][k] = 0.f;

    // prologue: chunks 0,1 into stages 0,1
    issue_chunk(Ab, Bb, s0, s0 + STAGE_A, 0, tid);
    asm volatile("cp.async.commit_group;" ::: "memory");
    issue_chunk(Ab, Bb, s0 + STAGE_SZ, s0 + STAGE_SZ + STAGE_A, 1, tid);
    asm volatile("cp.async.commit_group;" ::: "memory");

    int st_comp = 0;   // stage of chunk c
    int st_iss  = 2;   // stage of chunk c+2

    for (int c = 0; c < DIM / BK; c++) {
        if (c < DIM / BK - 1) {
            asm volatile("cp.async.wait_group 1;" ::: "memory");
        } else {
            asm volatile("cp.async.wait_group 0;" ::: "memory");
        }
        __syncthreads();

        if (c + 2 < DIM / BK) {
            uint32_t sb = s0 + st_iss * STAGE_SZ;
            issue_chunk(Ab, Bb, sb, sb + STAGE_A, c + 2, tid);
            asm volatile("cp.async.commit_group;" ::: "memory");
        }

        const uint32_t baseA = s0 + st_comp * STAGE_SZ;
        const uint32_t baseB = baseA + STAGE_A;
#pragma unroll
        for (int ks = 0; ks < 2; ks++) {
            const uint32_t kb = (uint32_t)(ks * 16);
            uint32_t a[2][4];
#pragma unroll
            for (int mt = 0; mt < 2; mt++) {
                uint32_t addr = baseA + (aRow + mt * 16) * (PITCH * 2) + (kb + aCol) * 2;
                LDSM4(a[mt][0], a[mt][1], a[mt][2], a[mt][3], addr);
            }
            uint32_t b[4][4];
#pragma unroll
            for (int nq = 0; nq < 4; nq++) {
                uint32_t addr = baseB + (bRow + nq * 16) * (PITCH * 2) + (kb + bCol) * 2;
                LDSM4(b[nq][0], b[nq][1], b[nq][2], b[nq][3], addr);
            }
#pragma unroll
            for (int mt = 0; mt < 2; mt++)
#pragma unroll
                for (int nt = 0; nt < 8; nt++)
                    MMA_BF16(acc[mt][nt], a[mt], b[nt >> 1][(nt & 1) * 2],
                             b[nt >> 1][(nt & 1) * 2 + 1]);
        }
        if (++st_comp == NSTAGES) st_comp = 0;
        if (++st_iss  == NSTAGES) st_iss  = 0;
    }

    // ---- epilogue: per-row base-2 LSE over this 128-col tile ----
    // part buffer at smem offset 0 (stage 0 A); last compute used stage 2.
    float2* part = (float2*)smem;

#pragma unroll
    for (int mt = 0; mt < 2; mt++) {
#pragma unroll
        for (int hf = 0; hf < 2; hf++) {
            float m = -1e30f;
            float e[16];
#pragma unroll
            for (int nt = 0; nt < 8; nt++) {
                e[nt * 2 + 0] = acc[mt][nt][hf * 2 + 0] * C1;
                e[nt * 2 + 1] = acc[mt][nt][hf * 2 + 1] * C1;
                m = fmaxf(m, fmaxf(e[nt * 2], e[nt * 2 + 1]));
            }
            float s = 0.f;
#pragma unroll
            for (int k = 0; k < 16; k++) s += ex2f(e[k] - m);
#pragma unroll
            for (int off = 1; off <= 2; off <<= 1) {
                float om = __shfl_xor_sync(0xffffffffu, m, off);
                float os = __shfl_xor_sync(0xffffffffu, s, off);
                float nm = fmaxf(m, om);
                s = s * ex2f(m - nm) + os * ex2f(om - nm);
                m = nm;
            }
            if ((lane & 3) == 0) {
                int row = wm * 32 + mt * 16 + hf * 8 + (lane >> 2);
                part[wn * 128 + row] = make_float2(m, s);
            }
        }
    }
    __syncthreads();
    if (tid < 128) {
        float2 p0 = part[tid];
        float2 p1 = part[128 + tid];
        float M = fmaxf(p0.x, p1.x);
        float S = p0.y * ex2f(p0.x - M) + p1.y * ex2f(p1.x - M);
        const int row = bm * BM + tid;
        g_pmax[bn * NROWS + row] = M;
        g_psum[bn * NROWS + row] = S;
    }
}

// ---------------------------------------------------------------------------
// diag + Hungarian path (bids 2048..2303): exact fp32 16x16 block, then
// warp-0 Jonker-Volgenant with redux.sync argmin (deterministic, exact min,
// lowest-index tie-break -> warp-uniform control flow).
// ---------------------------------------------------------------------------
__device__ void diag_jv_path(const float* __restrict__ O, const float* __restrict__ P,
                             int b, uint8_t* smem)
{
    float* so  = (float*)smem;                 // [16][257]
    float* sp  = (float*)(smem + 16448);       // [16][257]
    float* blk = (float*)(smem + 32896);       // [256]
    float* su  = (float*)(smem + 33920);       // [17]
    int*   spp = (int*)  (smem + 33988);       // [17]
    int*   swy = (int*)  (smem + 34056);       // [17]

    const int tid = threadIdx.x;
    const int i = tid >> 4;
    const int j = tid & 15;

    float acc = 0.f;
    for (int k0 = 0; k0 < DIM; k0 += 256) {
        for (int t = tid; t < 16 * 256; t += 256) {
            int r = t >> 8, c = t & 255;
            so[r * 257 + c] = O[(size_t)(b * 16 + r) * DIM + k0 + c];
            sp[r * 257 + c] = P[(size_t)(b * 16 + r) * DIM + k0 + c];
        }
        __syncthreads();
#pragma unroll 8
        for (int k = 0; k < 256; k++) acc += so[i * 257 + k] * sp[j * 257 + k];
        __syncthreads();
    }
    blk[tid] = acc * SCALE;
    __syncthreads();
    if (tid >= 32) return;

    // ---- warp JV on -blk ----
    const int lane = tid;
    if (lane < 17) { su[lane] = 0.f; spp[lane] = 0; }
    float v = 0.f;                 // lane<16: potential of column lane+1
    __syncwarp();

    for (int ii = 1; ii <= 16; ii++) {
        if (lane == 0) spp[0] = ii;
        float minv = 1e30f;
        int   wayr = 0;
        unsigned used = 0u;
        int j0 = 0;
        __syncwarp();

        for (int guard = 0; guard <= 16; guard++) {
            used |= (1u << j0);
            const int i0  = spp[j0];
            const float ui0 = su[i0];

            bool act = (lane < 16) && !((used >> (lane + 1)) & 1u);
            if (act) {
                float cur = -blk[(i0 - 1) * 16 + lane] - ui0 - v;
                if (cur < minv) { minv = cur; wayr = j0; }
            }
            unsigned ou = act ? ordf(minv) : 0xFFFFFFFFu;
            unsigned mn = __reduce_min_sync(0xffffffffu, ou);
            unsigned bl = __ballot_sync(0xffffffffu, ou == mn);
            int   jm = __ffs(bl);          // winner lane + 1 == column index
            float d  = unordf(mn);

            if (lane < 16) {
                if ((used >> (lane + 1)) & 1u) { v -= d; su[spp[lane + 1]] += d; }
                else                           { minv -= d; }
            } else if (lane == 16) {
                su[spp[0]] += d;           // virtual column 0 always used
            }
            __syncwarp();
            j0 = jm;
            if (spp[j0] == 0) break;
        }

        if (lane < 16) swy[lane + 1] = wayr;
        __syncwarp();
        if (lane == 0) {
            int jj = j0;
            while (jj) { int j1 = swy[jj]; spp[jj] = spp[j1]; jj = j1; }
        }
        __syncwarp();
    }

    if (lane < 16) {
        const int row = spp[lane + 1] - 1;   // row matched to column lane
        g_matched[b * 16 + row] = blk[row * 16 + lane];
    }
}

// ---------------------------------------------------------------------------
// Kernel 1: fused GEMM + diag/JV.
// ---------------------------------------------------------------------------
__global__ __launch_bounds__(256) void fused_kernel(
    const float* __restrict__ O, const float* __restrict__ P)
{
    extern __shared__ __align__(16) uint8_t dynsmem[];
    if (blockIdx.x < GEMM_CTAS) gemm_path(dynsmem, blockIdx.x);
    else                        diag_jv_path(O, P, blockIdx.x - GEMM_CTAS, dynsmem);
}

// ---------------------------------------------------------------------------
// Kernel 2: per-row loss + fused deterministic mean (last-block sum).
// LSE_nat(r) = ln2 * (M2 + log2(sum_t s_t * 2^(m_t - M2)))
// ---------------------------------------------------------------------------
__global__ __launch_bounds__(128) void finalize_kernel(float* __restrict__ out)
{
    __shared__ float red[128];
    __shared__ unsigned lastf;
    const int row = blockIdx.x * 128 + threadIdx.x;
    float M = -1e30f;
#pragma unroll 8
    for (int t = 0; t < NTILE; t++) M = fmaxf(M, g_pmax[t * NROWS + row]);
    float S = 0.f;
#pragma unroll 8
    for (int t = 0; t < NTILE; t++)
        S += g_psum[t * NROWS + row] * ex2f(g_pmax[t * NROWS + row] - M);
    red[threadIdx.x] = LN2f * (M + lg2f(S)) - g_matched[row];
    __syncthreads();
    for (int s = 64; s; s >>= 1) {
        if (threadIdx.x < s) red[threadIdx.x] += red[threadIdx.x + s];
        __syncthreads();
    }
    if (threadIdx.x == 0) {
        g_partial[blockIdx.x] = red[0];
        __threadfence();
        lastf = (atomicAdd(&g_done, 1u) == (NROWS / 128 - 1));
    }
    __syncthreads();
    if (lastf && threadIdx.x == 0) {
        float s = 0.f;
#pragma unroll
        for (int i = 0; i < NROWS / 128; i++) s += g_partial[i];
        out[0] = s * (1.0f / (float)NROWS);
        g_done = 0;                 // reset for next graph replay
    }
}

// ---------------------------------------------------------------------------
extern "C" void kernel_launch(void* const* d_in, const int* in_sizes, int n_in,
                              void* d_out, int out_size)
{
    const float* O  = (const float*)d_in[0];
    const float* P  = (const float*)d_in[1];
    const float* Ng = (const float*)d_in[2];
    float* out = (float*)d_out;

    static int attr_set = 0;
    if (!attr_set) {
        cudaFuncSetAttribute(fused_kernel,
                             cudaFuncAttributeMaxDynamicSharedMemorySize, SMEM_DYN);
        attr_set = 1;
    }

    convert_kernel<<<2048, 256>>>((const float4*)O, (const float4*)P,
                                  (const float4*)Ng);
    fused_kernel<<<TOTAL_CTAS, 256, SMEM_DYN>>>(O, P);
    finalize_kernel<<<NROWS / 128, 128>>>(out);
}

// round 14
// speedup vs baseline: 6.2482x; 1.0215x over previous
#include <cuda_runtime.h>
#include <cuda_bf16.h>
#include <math.h>
#include <stdint.h>

// ---------------------------------------------------------------------------
// HungarianContrastiveLoss on GB300 (sm_103 base-ISA tensor cores)
//   sim = (O/0.05) @ [P;Ng]^T   (4096 x 8192, K=1024)
//   loss = mean_r( LSE(sim[r,:]) - sim[r, hungarian_col(r)] )
//
//   K0 convert: fp32 -> bf16 copies of O and E=[P;Ng]
//   K1 fused:   bids 0..255   : exact fp32 diag 16x16 block + warp JV
//                               (FIRST so they overlap the GEMM body)
//               bids 256..2303: bf16 mma.sync GEMM (128x128 tile, 3-stage
//                               cp.async) + streaming base-2 LSE partials
//   K2 finalize: per-row loss + fused deterministic mean (last-block sum)
// ---------------------------------------------------------------------------

#define NROWS  4096
#define NCOLSS 8192
#define DIM    1024
#define NTILE  64            // 8192 / 128 column tiles
#define SCALE  20.0f
#define C1     28.853900817779268f   // 20 * log2(e)
#define LN2f   0.6931471805599453f

#define BM 128
#define BN 128
#define BK 32
#define PITCH 40             // halves per SMEM row (80 B: 5 mod 8 -> no LDSM conflicts)

#define STAGE_A  (BM * PITCH * 2)          // 10240 B
#define STAGE_B  (BN * PITCH * 2)          // 10240 B
#define STAGE_SZ (STAGE_A + STAGE_B)       // 20480 B
#define NSTAGES  3
#define SMEM_DYN (NSTAGES * STAGE_SZ)      // 61440 B

#define DIAG_CTAS 256
#define GEMM_CTAS (NTILE * (NROWS / BM))   // 2048
#define TOTAL_CTAS (GEMM_CTAS + DIAG_CTAS)

// device-global scratch (allocation-free rule)
__device__ __nv_bfloat16 g_Obf[NROWS * DIM];
__device__ __nv_bfloat16 g_Ebf[NCOLSS * DIM];   // rows 0..4095 = P, 4096..8191 = Ng
__device__ float g_pmax[NTILE * NROWS];
__device__ float g_psum[NTILE * NROWS];
__device__ float g_matched[NROWS];
__device__ float g_partial[32];
__device__ unsigned g_done;                     // zero-init; reset by last block

// ---------------------------------------------------------------------------
// helpers
// ---------------------------------------------------------------------------
__device__ __forceinline__ uint32_t smem_u32(const void* p) {
    uint32_t a;
    asm("{ .reg .u64 t; cvta.to.shared.u64 t, %1; cvt.u32.u64 %0, t; }" : "=r"(a) : "l"(p));
    return a;
}
__device__ __forceinline__ void cp16(uint32_t dst, const void* src) {
    asm volatile("cp.async.cg.shared.global [%0], [%1], 16;" :: "r"(dst), "l"(src));
}
__device__ __forceinline__ float ex2f(float x) {
    float y; asm("ex2.approx.f32 %0, %1;" : "=f"(y) : "f"(x)); return y;
}
__device__ __forceinline__ float lg2f(float x) {
    float y; asm("lg2.approx.f32 %0, %1;" : "=f"(y) : "f"(x)); return y;
}
// order-preserving float <-> uint (for redux.sync.min on floats)
__device__ __forceinline__ unsigned ordf(float f) {
    unsigned u = __float_as_uint(f);
    return (u & 0x80000000u) ? ~u : (u | 0x80000000u);
}
__device__ __forceinline__ float unordf(unsigned u) {
    u = (u & 0x80000000u) ? (u & 0x7FFFFFFFu) : ~u;
    return __uint_as_float(u);
}
#define LDSM4(R0, R1, R2, R3, ADDR)                                             \
    asm volatile("ldmatrix.sync.aligned.m8n8.x4.shared.b16 {%0,%1,%2,%3}, [%4];"\
                 : "=r"(R0), "=r"(R1), "=r"(R2), "=r"(R3) : "r"(ADDR))

#define MMA_BF16(D, A, B0, B1)                                                  \
    asm volatile("mma.sync.aligned.m16n8k16.row.col.f32.bf16.bf16.f32 "         \
                 "{%0,%1,%2,%3}, {%4,%5,%6,%7}, {%8,%9}, {%0,%1,%2,%3};"        \
                 : "+f"((D)[0]), "+f"((D)[1]), "+f"((D)[2]), "+f"((D)[3])       \
                 : "r"((A)[0]), "r"((A)[1]), "r"((A)[2]), "r"((A)[3]),          \
                   "r"(B0), "r"(B1))

// ---------------------------------------------------------------------------
// Kernel 0: fp32 -> bf16 conversion (read-once / write-once streaming).
// ---------------------------------------------------------------------------
__global__ __launch_bounds__(256) void convert_kernel(
    const float4* __restrict__ O, const float4* __restrict__ P,
    const float4* __restrict__ Ng)
{
    const int N4 = NROWS * DIM / 4;   // per tensor
    uint2* ob = (uint2*)g_Obf;
    uint2* eb = (uint2*)g_Ebf;
    for (int i = blockIdx.x * 256 + threadIdx.x; i < 3 * N4; i += gridDim.x * 256) {
        const float4* src; uint2* dst;
        if (i < N4)           { src = O + i;            dst = ob + i; }
        else if (i < 2 * N4)  { int j = i - N4;         src = P + j;  dst = eb + j; }
        else                  { int j = i - 2 * N4;     src = Ng + j; dst = eb + N4 + j; }
        float4 v;
        asm volatile("ld.global.nc.v4.f32 {%0,%1,%2,%3}, [%4];"
                     : "=f"(v.x), "=f"(v.y), "=f"(v.z), "=f"(v.w) : "l"(src));
        __nv_bfloat162 lo = __float22bfloat162_rn(make_float2(v.x, v.y));
        __nv_bfloat162 hi = __float22bfloat162_rn(make_float2(v.z, v.w));
        uint2 o = make_uint2(*(uint32_t*)&lo, *(uint32_t*)&hi);
        asm volatile("st.global.cs.v2.b32 [%0], {%1,%2};" :: "l"(dst), "r"(o.x), "r"(o.y));
    }
}

// ---------------------------------------------------------------------------
// GEMM tile path (bids 256..2303 -> tile id 0..2047)
// ---------------------------------------------------------------------------
__device__ __forceinline__ void issue_chunk(
    const __nv_bfloat16* __restrict__ Ab, const __nv_bfloat16* __restrict__ Bb,
    uint32_t sA, uint32_t sB, int chunk, int tid)
{
    const int gk = chunk * BK;
#pragma unroll
    for (int it = 0; it < 2; it++) {
        int idx = it * 256 + tid;          // 0..511
        int r = idx >> 2;                  // row 0..127
        int q = idx & 3;                   // 8-half quarter
        cp16(sA + r * (PITCH * 2) + q * 16, Ab + (size_t)r * DIM + gk + q * 8);
        cp16(sB + r * (PITCH * 2) + q * 16, Bb + (size_t)r * DIM + gk + q * 8);
    }
}

__device__ void gemm_path(uint8_t* smem, int bid)
{
    const int tid  = threadIdx.x;
    const int lane = tid & 31;
    const int wid  = tid >> 5;
    const int wm   = wid & 3;      // 0..3 (m)
    const int wn   = wid >> 2;     // 0..1 (n)
    const int bn = bid & (NTILE - 1);
    const int bm = bid >> 6;

    const __nv_bfloat16* Ab = g_Obf + (size_t)bm * BM * DIM;
    const __nv_bfloat16* Bb = g_Ebf + (size_t)bn * BN * DIM;

    const uint32_t s0 = smem_u32(smem);

    const uint32_t aRow = (uint32_t)(wm * 32 + (lane & 7) + ((lane >> 3) & 1) * 8);
    const uint32_t aCol = (uint32_t)((lane >> 4) * 8);
    const uint32_t bRow = (uint32_t)(wn * 64 + (lane & 7) + (lane >> 4) * 8);
    const uint32_t bCol = (uint32_t)(((lane >> 3) & 1) * 8);

    float acc[2][8][4];
#pragma unroll
    for (int mt = 0; mt < 2; mt++)
#pragma unroll
        for (int nt = 0; nt < 8; nt++)
#pragma unroll
            for (int k = 0; k < 4; k++) acc[mt][nt][k] = 0.f;

    // prologue: chunks 0,1 into stages 0,1
    issue_chunk(Ab, Bb, s0, s0 + STAGE_A, 0, tid);
    asm volatile("cp.async.commit_group;" ::: "memory");
    issue_chunk(Ab, Bb, s0 + STAGE_SZ, s0 + STAGE_SZ + STAGE_A, 1, tid);
    asm volatile("cp.async.commit_group;" ::: "memory");

    int st_comp = 0;   // stage of chunk c
    int st_iss  = 2;   // stage of chunk c+2

    for (int c = 0; c < DIM / BK; c++) {
        if (c < DIM / BK - 1) {
            asm volatile("cp.async.wait_group 1;" ::: "memory");
        } else {
            asm volatile("cp.async.wait_group 0;" ::: "memory");
        }
        __syncthreads();

        if (c + 2 < DIM / BK) {
            uint32_t sb = s0 + st_iss * STAGE_SZ;
            issue_chunk(Ab, Bb, sb, sb + STAGE_A, c + 2, tid);
            asm volatile("cp.async.commit_group;" ::: "memory");
        }

        const uint32_t baseA = s0 + st_comp * STAGE_SZ;
        const uint32_t baseB = baseA + STAGE_A;
#pragma unroll
        for (int ks = 0; ks < 2; ks++) {
            const uint32_t kb = (uint32_t)(ks * 16);
            uint32_t a[2][4];
#pragma unroll
            for (int mt = 0; mt < 2; mt++) {
                uint32_t addr = baseA + (aRow + mt * 16) * (PITCH * 2) + (kb + aCol) * 2;
                LDSM4(a[mt][0], a[mt][1], a[mt][2], a[mt][3], addr);
            }
            uint32_t b[4][4];
#pragma unroll
            for (int nq = 0; nq < 4; nq++) {
                uint32_t addr = baseB + (bRow + nq * 16) * (PITCH * 2) + (kb + bCol) * 2;
                LDSM4(b[nq][0], b[nq][1], b[nq][2], b[nq][3], addr);
            }
#pragma unroll
            for (int mt = 0; mt < 2; mt++)
#pragma unroll
                for (int nt = 0; nt < 8; nt++)
                    MMA_BF16(acc[mt][nt], a[mt], b[nt >> 1][(nt & 1) * 2],
                             b[nt >> 1][(nt & 1) * 2 + 1]);
        }
        if (++st_comp == NSTAGES) st_comp = 0;
        if (++st_iss  == NSTAGES) st_iss  = 0;
    }

    // ---- epilogue: per-row base-2 LSE over this 128-col tile ----
    float2* part = (float2*)smem;

#pragma unroll
    for (int mt = 0; mt < 2; mt++) {
#pragma unroll
        for (int hf = 0; hf < 2; hf++) {
            float m = -1e30f;
            float e[16];
#pragma unroll
            for (int nt = 0; nt < 8; nt++) {
                e[nt * 2 + 0] = acc[mt][nt][hf * 2 + 0] * C1;
                e[nt * 2 + 1] = acc[mt][nt][hf * 2 + 1] * C1;
                m = fmaxf(m, fmaxf(e[nt * 2], e[nt * 2 + 1]));
            }
            float s = 0.f;
#pragma unroll
            for (int k = 0; k < 16; k++) s += ex2f(e[k] - m);
#pragma unroll
            for (int off = 1; off <= 2; off <<= 1) {
                float om = __shfl_xor_sync(0xffffffffu, m, off);
                float os = __shfl_xor_sync(0xffffffffu, s, off);
                float nm = fmaxf(m, om);
                s = s * ex2f(m - nm) + os * ex2f(om - nm);
                m = nm;
            }
            if ((lane & 3) == 0) {
                int row = wm * 32 + mt * 16 + hf * 8 + (lane >> 2);
                part[wn * 128 + row] = make_float2(m, s);
            }
        }
    }
    __syncthreads();
    if (tid < 128) {
        float2 p0 = part[tid];
        float2 p1 = part[128 + tid];
        float M = fmaxf(p0.x, p1.x);
        float S = p0.y * ex2f(p0.x - M) + p1.y * ex2f(p1.x - M);
        const int row = bm * BM + tid;
        g_pmax[bn * NROWS + row] = M;
        g_psum[bn * NROWS + row] = S;
    }
}

// ---------------------------------------------------------------------------
// diag + Hungarian path (bids 0..255, scheduled FIRST so the ~40us JV
// latency overlaps the MMA-bound GEMM body instead of trailing it).
// ---------------------------------------------------------------------------
__device__ void diag_jv_path(const float* __restrict__ O, const float* __restrict__ P,
                             int b, uint8_t* smem)
{
    float* so  = (float*)smem;                 // [16][257]
    float* sp  = (float*)(smem + 16448);       // [16][257]
    float* blk = (float*)(smem + 32896);       // [256]
    float* su  = (float*)(smem + 33920);       // [17]
    int*   spp = (int*)  (smem + 33988);       // [17]
    int*   swy = (int*)  (smem + 34056);       // [17]

    const int tid = threadIdx.x;
    const int i = tid >> 4;
    const int j = tid & 15;

    float acc = 0.f;
    for (int k0 = 0; k0 < DIM; k0 += 256) {
        for (int t = tid; t < 16 * 256; t += 256) {
            int r = t >> 8, c = t & 255;
            so[r * 257 + c] = O[(size_t)(b * 16 + r) * DIM + k0 + c];
            sp[r * 257 + c] = P[(size_t)(b * 16 + r) * DIM + k0 + c];
        }
        __syncthreads();
#pragma unroll 8
        for (int k = 0; k < 256; k++) acc += so[i * 257 + k] * sp[j * 257 + k];
        __syncthreads();
    }
    blk[tid] = acc * SCALE;
    __syncthreads();
    if (tid >= 32) return;

    // ---- warp JV on -blk ----
    const int lane = tid;
    if (lane < 17) { su[lane] = 0.f; spp[lane] = 0; }
    float v = 0.f;                 // lane<16: potential of column lane+1
    __syncwarp();

    for (int ii = 1; ii <= 16; ii++) {
        if (lane == 0) spp[0] = ii;
        float minv = 1e30f;
        int   wayr = 0;
        unsigned used = 0u;
        int j0 = 0;
        __syncwarp();

        for (int guard = 0; guard <= 16; guard++) {
            used |= (1u << j0);
            const int i0  = spp[j0];
            const float ui0 = su[i0];

            bool act = (lane < 16) && !((used >> (lane + 1)) & 1u);
            if (act) {
                float cur = -blk[(i0 - 1) * 16 + lane] - ui0 - v;
                if (cur < minv) { minv = cur; wayr = j0; }
            }
            unsigned ou = act ? ordf(minv) : 0xFFFFFFFFu;
            unsigned mn = __reduce_min_sync(0xffffffffu, ou);
            unsigned bl = __ballot_sync(0xffffffffu, ou == mn);
            int   jm = __ffs(bl);          // winner lane + 1 == column index
            float d  = unordf(mn);

            if (lane < 16) {
                if ((used >> (lane + 1)) & 1u) { v -= d; su[spp[lane + 1]] += d; }
                else                           { minv -= d; }
            } else if (lane == 16) {
                su[spp[0]] += d;           // virtual column 0 always used
            }
            __syncwarp();
            j0 = jm;
            if (spp[j0] == 0) break;
        }

        if (lane < 16) swy[lane + 1] = wayr;
        __syncwarp();
        if (lane == 0) {
            int jj = j0;
            while (jj) { int j1 = swy[jj]; spp[jj] = spp[j1]; jj = j1; }
        }
        __syncwarp();
    }

    if (lane < 16) {
        const int row = spp[lane + 1] - 1;   // row matched to column lane
        g_matched[b * 16 + row] = blk[row * 16 + lane];
    }
}

// ---------------------------------------------------------------------------
// Kernel 1: fused diag/JV (first) + GEMM.
// ---------------------------------------------------------------------------
__global__ __launch_bounds__(256) void fused_kernel(
    const float* __restrict__ O, const float* __restrict__ P)
{
    extern __shared__ __align__(16) uint8_t dynsmem[];
    if (blockIdx.x < DIAG_CTAS) diag_jv_path(O, P, blockIdx.x, dynsmem);
    else                        gemm_path(dynsmem, blockIdx.x - DIAG_CTAS);
}

// ---------------------------------------------------------------------------
// Kernel 2: per-row loss + fused deterministic mean (last-block sum).
// LSE_nat(r) = ln2 * (M2 + log2(sum_t s_t * 2^(m_t - M2)))
// ---------------------------------------------------------------------------
__global__ __launch_bounds__(128) void finalize_kernel(float* __restrict__ out)
{
    __shared__ float red[128];
    __shared__ unsigned lastf;
    const int row = blockIdx.x * 128 + threadIdx.x;
    float M = -1e30f;
#pragma unroll 8
    for (int t = 0; t < NTILE; t++) M = fmaxf(M, g_pmax[t * NROWS + row]);
    float S = 0.f;
#pragma unroll 8
    for (int t = 0; t < NTILE; t++)
        S += g_psum[t * NROWS + row] * ex2f(g_pmax[t * NROWS + row] - M);
    red[threadIdx.x] = LN2f * (M + lg2f(S)) - g_matched[row];
    __syncthreads();
    for (int s = 64; s; s >>= 1) {
        if (threadIdx.x < s) red[threadIdx.x] += red[threadIdx.x + s];
        __syncthreads();
    }
    if (threadIdx.x == 0) {
        g_partial[blockIdx.x] = red[0];
        __threadfence();
        lastf = (atomicAdd(&g_done, 1u) == (NROWS / 128 - 1));
    }
    __syncthreads();
    if (lastf && threadIdx.x == 0) {
        float s = 0.f;
#pragma unroll
        for (int i = 0; i < NROWS / 128; i++) s += g_partial[i];
        out[0] = s * (1.0f / (float)NROWS);
        g_done = 0;                 // reset for next graph replay
    }
}

// ---------------------------------------------------------------------------
extern "C" void kernel_launch(void* const* d_in, const int* in_sizes, int n_in,
                              void* d_out, int out_size)
{
    const float* O  = (const float*)d_in[0];
    const float* P  = (const float*)d_in[1];
    const float* Ng = (const float*)d_in[2];
    float* out = (float*)d_out;

    static int attr_set = 0;
    if (!attr_set) {
        cudaFuncSetAttribute(fused_kernel,
                             cudaFuncAttributeMaxDynamicSharedMemorySize, SMEM_DYN);
        attr_set = 1;
    }

    convert_kernel<<<2048, 256>>>((const float4*)O, (const float4*)P,
                                  (const float4*)Ng);
    fused_kernel<<<TOTAL_CTAS, 256, SMEM_DYN>>>(O, P);
    finalize_kernel<<<NROWS / 128, 128>>>(out);
}

// round 16
// speedup vs baseline: 6.5576x; 1.0495x over previous
#include <cuda_runtime.h>
#include <cuda_bf16.h>
#include <math.h>
#include <stdint.h>

// ---------------------------------------------------------------------------
// HungarianContrastiveLoss on GB300 (sm_103 base-ISA tensor cores)
//   sim = (O/0.05) @ [P;Ng]^T   (4096 x 8192, K=1024)
//   loss = mean_r( LSE(sim[r,:]) - sim[r, hungarian_col(r)] )
//
//   K0 convert: fp32 -> bf16 copies of O and E=[P;Ng]
//   K1 fused:   bids 0..31    : 8 batches per CTA — diag 16x16 blocks
//                               (cooperative) + 8 concurrent warp-JVs.
//                               Only 32 CTA slots blocked -> GEMM stays fed.
//               bids 32..2079 : bf16 mma.sync GEMM (128x128 tile, 3-stage
//                               cp.async) + streaming base-2 LSE partials
//   K2 finalize: per-row loss + fused deterministic mean (last-block sum)
// ---------------------------------------------------------------------------

#define NROWS  4096
#define NCOLSS 8192
#define DIM    1024
#define NTILE  64            // 8192 / 128 column tiles
#define SCALE  20.0f
#define C1     28.853900817779268f   // 20 * log2(e)
#define LN2f   0.6931471805599453f

#define BM 128
#define BN 128
#define BK 32
#define PITCH 40             // halves per SMEM row (80 B: 5 mod 8 -> no LDSM conflicts)

#define STAGE_A  (BM * PITCH * 2)          // 10240 B
#define STAGE_B  (BN * PITCH * 2)          // 10240 B
#define STAGE_SZ (STAGE_A + STAGE_B)       // 20480 B
#define NSTAGES  3
#define SMEM_DYN (NSTAGES * STAGE_SZ)      // 61440 B

#define DIAG_CTAS 32                       // 8 batches per CTA
#define GEMM_CTAS (NTILE * (NROWS / BM))   // 2048
#define TOTAL_CTAS (GEMM_CTAS + DIAG_CTAS)

// device-global scratch (allocation-free rule)
__device__ __nv_bfloat16 g_Obf[NROWS * DIM];
__device__ __nv_bfloat16 g_Ebf[NCOLSS * DIM];   // rows 0..4095 = P, 4096..8191 = Ng
__device__ float g_pmax[NTILE * NROWS];
__device__ float g_psum[NTILE * NROWS];
__device__ float g_matched[NROWS];
__device__ float g_partial[32];
__device__ unsigned g_done;                     // zero-init; reset by last block

// ---------------------------------------------------------------------------
// helpers
// ---------------------------------------------------------------------------
__device__ __forceinline__ uint32_t smem_u32(const void* p) {
    uint32_t a;
    asm("{ .reg .u64 t; cvta.to.shared.u64 t, %1; cvt.u32.u64 %0, t; }" : "=r"(a) : "l"(p));
    return a;
}
__device__ __forceinline__ void cp16(uint32_t dst, const void* src) {
    asm volatile("cp.async.cg.shared.global [%0], [%1], 16;" :: "r"(dst), "l"(src));
}
__device__ __forceinline__ float ex2f(float x) {
    float y; asm("ex2.approx.f32 %0, %1;" : "=f"(y) : "f"(x)); return y;
}
__device__ __forceinline__ float lg2f(float x) {
    float y; asm("lg2.approx.f32 %0, %1;" : "=f"(y) : "f"(x)); return y;
}
// order-preserving float <-> uint (for redux.sync.min on floats)
__device__ __forceinline__ unsigned ordf(float f) {
    unsigned u = __float_as_uint(f);
    return (u & 0x80000000u) ? ~u : (u | 0x80000000u);
}
__device__ __forceinline__ float unordf(unsigned u) {
    u = (u & 0x80000000u) ? (u & 0x7FFFFFFFu) : ~u;
    return __uint_as_float(u);
}
#define LDSM4(R0, R1, R2, R3, ADDR)                                             \
    asm volatile("ldmatrix.sync.aligned.m8n8.x4.shared.b16 {%0,%1,%2,%3}, [%4];"\
                 : "=r"(R0), "=r"(R1), "=r"(R2), "=r"(R3) : "r"(ADDR))

#define MMA_BF16(D, A, B0, B1)                                                  \
    asm volatile("mma.sync.aligned.m16n8k16.row.col.f32.bf16.bf16.f32 "         \
                 "{%0,%1,%2,%3}, {%4,%5,%6,%7}, {%8,%9}, {%0,%1,%2,%3};"        \
                 : "+f"((D)[0]), "+f"((D)[1]), "+f"((D)[2]), "+f"((D)[3])       \
                 : "r"((A)[0]), "r"((A)[1]), "r"((A)[2]), "r"((A)[3]),          \
                   "r"(B0), "r"(B1))

// ---------------------------------------------------------------------------
// Kernel 0: fp32 -> bf16 conversion (read-once / write-once streaming).
// ---------------------------------------------------------------------------
__global__ __launch_bounds__(256) void convert_kernel(
    const float4* __restrict__ O, const float4* __restrict__ P,
    const float4* __restrict__ Ng)
{
    const int N4 = NROWS * DIM / 4;   // per tensor
    uint2* ob = (uint2*)g_Obf;
    uint2* eb = (uint2*)g_Ebf;
    for (int i = blockIdx.x * 256 + threadIdx.x; i < 3 * N4; i += gridDim.x * 256) {
        const float4* src; uint2* dst;
        if (i < N4)           { src = O + i;            dst = ob + i; }
        else if (i < 2 * N4)  { int j = i - N4;         src = P + j;  dst = eb + j; }
        else                  { int j = i - 2 * N4;     src = Ng + j; dst = eb + N4 + j; }
        float4 v;
        asm volatile("ld.global.nc.v4.f32 {%0,%1,%2,%3}, [%4];"
                     : "=f"(v.x), "=f"(v.y), "=f"(v.z), "=f"(v.w) : "l"(src));
        __nv_bfloat162 lo = __float22bfloat162_rn(make_float2(v.x, v.y));
        __nv_bfloat162 hi = __float22bfloat162_rn(make_float2(v.z, v.w));
        uint2 o = make_uint2(*(uint32_t*)&lo, *(uint32_t*)&hi);
        asm volatile("st.global.cs.v2.b32 [%0], {%1,%2};" :: "l"(dst), "r"(o.x), "r"(o.y));
    }
}

// ---------------------------------------------------------------------------
// GEMM tile path (bids 32..2079 -> tile id 0..2047)
// ---------------------------------------------------------------------------
__device__ __forceinline__ void issue_chunk(
    const __nv_bfloat16* __restrict__ Ab, const __nv_bfloat16* __restrict__ Bb,
    uint32_t sA, uint32_t sB, int chunk, int tid)
{
    const int gk = chunk * BK;
#pragma unroll
    for (int it = 0; it < 2; it++) {
        int idx = it * 256 + tid;          // 0..511
        int r = idx >> 2;                  // row 0..127
        int q = idx & 3;                   // 8-half quarter
        cp16(sA + r * (PITCH * 2) + q * 16, Ab + (size_t)r * DIM + gk + q * 8);
        cp16(sB + r * (PITCH * 2) + q * 16, Bb + (size_t)r * DIM + gk + q * 8);
    }
}

__device__ void gemm_path(uint8_t* smem, int bid)
{
    const int tid  = threadIdx.x;
    const int lane = tid & 31;
    const int wid  = tid >> 5;
    const int wm   = wid & 3;      // 0..3 (m)
    const int wn   = wid >> 2;     // 0..1 (n)
    const int bn = bid & (NTILE - 1);
    const int bm = bid >> 6;

    const __nv_bfloat16* Ab = g_Obf + (size_t)bm * BM * DIM;
    const __nv_bfloat16* Bb = g_Ebf + (size_t)bn * BN * DIM;

    const uint32_t s0 = smem_u32(smem);

    const uint32_t aRow = (uint32_t)(wm * 32 + (lane & 7) + ((lane >> 3) & 1) * 8);
    const uint32_t aCol = (uint32_t)((lane >> 4) * 8);
    const uint32_t bRow = (uint32_t)(wn * 64 + (lane & 7) + (lane >> 4) * 8);
    const uint32_t bCol = (uint32_t)(((lane >> 3) & 1) * 8);

    float acc[2][8][4];
#pragma unroll
    for (int mt = 0; mt < 2; mt++)
#pragma unroll
        for (int nt = 0; nt < 8; nt++)
#pragma unroll
            for (int k = 0; k < 4; k++) acc[mt][nt][k] = 0.f;

    // prologue: chunks 0,1 into stages 0,1
    issue_chunk(Ab, Bb, s0, s0 + STAGE_A, 0, tid);
    asm volatile("cp.async.commit_group;" ::: "memory");
    issue_chunk(Ab, Bb, s0 + STAGE_SZ, s0 + STAGE_SZ + STAGE_A, 1, tid);
    asm volatile("cp.async.commit_group;" ::: "memory");

    int st_comp = 0;   // stage of chunk c
    int st_iss  = 2;   // stage of chunk c+2

    for (int c = 0; c < DIM / BK; c++) {
        if (c < DIM / BK - 1) {
            asm volatile("cp.async.wait_group 1;" ::: "memory");
        } else {
            asm volatile("cp.async.wait_group 0;" ::: "memory");
        }
        __syncthreads();

        if (c + 2 < DIM / BK) {
            uint32_t sb = s0 + st_iss * STAGE_SZ;
            issue_chunk(Ab, Bb, sb, sb + STAGE_A, c + 2, tid);
            asm volatile("cp.async.commit_group;" ::: "memory");
        }

        const uint32_t baseA = s0 + st_comp * STAGE_SZ;
        const uint32_t baseB = baseA + STAGE_A;
#pragma unroll
        for (int ks = 0; ks < 2; ks++) {
            const uint32_t kb = (uint32_t)(ks * 16);
            uint32_t a[2][4];
#pragma unroll
            for (int mt = 0; mt < 2; mt++) {
                uint32_t addr = baseA + (aRow + mt * 16) * (PITCH * 2) + (kb + aCol) * 2;
                LDSM4(a[mt][0], a[mt][1], a[mt][2], a[mt][3], addr);
            }
            uint32_t b[4][4];
#pragma unroll
            for (int nq = 0; nq < 4; nq++) {
                uint32_t addr = baseB + (bRow + nq * 16) * (PITCH * 2) + (kb + bCol) * 2;
                LDSM4(b[nq][0], b[nq][1], b[nq][2], b[nq][3], addr);
            }
#pragma unroll
            for (int mt = 0; mt < 2; mt++)
#pragma unroll
                for (int nt = 0; nt < 8; nt++)
                    MMA_BF16(acc[mt][nt], a[mt], b[nt >> 1][(nt & 1) * 2],
                             b[nt >> 1][(nt & 1) * 2 + 1]);
        }
        if (++st_comp == NSTAGES) st_comp = 0;
        if (++st_iss  == NSTAGES) st_iss  = 0;
    }

    // ---- epilogue: per-row base-2 LSE over this 128-col tile ----
    float2* part = (float2*)smem;

#pragma unroll
    for (int mt = 0; mt < 2; mt++) {
#pragma unroll
        for (int hf = 0; hf < 2; hf++) {
            float m = -1e30f;
            float e[16];
#pragma unroll
            for (int nt = 0; nt < 8; nt++) {
                e[nt * 2 + 0] = acc[mt][nt][hf * 2 + 0] * C1;
                e[nt * 2 + 1] = acc[mt][nt][hf * 2 + 1] * C1;
                m = fmaxf(m, fmaxf(e[nt * 2], e[nt * 2 + 1]));
            }
            float s = 0.f;
#pragma unroll
            for (int k = 0; k < 16; k++) s += ex2f(e[k] - m);
#pragma unroll
            for (int off = 1; off <= 2; off <<= 1) {
                float om = __shfl_xor_sync(0xffffffffu, m, off);
                float os = __shfl_xor_sync(0xffffffffu, s, off);
                float nm = fmaxf(m, om);
                s = s * ex2f(m - nm) + os * ex2f(om - nm);
                m = nm;
            }
            if ((lane & 3) == 0) {
                int row = wm * 32 + mt * 16 + hf * 8 + (lane >> 2);
                part[wn * 128 + row] = make_float2(m, s);
            }
        }
    }
    __syncthreads();
    if (tid < 128) {
        float2 p0 = part[tid];
        float2 p1 = part[128 + tid];
        float M = fmaxf(p0.x, p1.x);
        float S = p0.y * ex2f(p0.x - M) + p1.y * ex2f(p1.x - M);
        const int row = bm * BM + tid;
        g_pmax[bn * NROWS + row] = M;
        g_psum[bn * NROWS + row] = S;
    }
}

// ---------------------------------------------------------------------------
// diag + Hungarian path, 8 BATCHES PER CTA (bids 0..31).
// Phase 1: all 256 threads compute the 8 diagonal 16x16 blocks sequentially.
// Phase 2: warp w runs the JV on batch w — 8 concurrent latency chains, so
// only 32 CTA slots are blocked instead of 256.
// ---------------------------------------------------------------------------
__device__ void diag_jv_path(const float* __restrict__ O, const float* __restrict__ P,
                             int cta, uint8_t* smem)
{
    float* so   = (float*)smem;                 // [16][257]  16448 B
    float* sp   = (float*)(smem + 16448);       // [16][257]  16448 B
    float* blk8 = (float*)(smem + 32896);       // [8][256]    8192 B
    float* su   = (float*)(smem + 41088);       // [8][17]      544 B
    int*   spp  = (int*)  (smem + 41632);       // [8][17]      544 B
    int*   swy  = (int*)  (smem + 42176);       // [8][17]      544 B

    const int tid = threadIdx.x;
    const int ti = tid >> 4;
    const int tj = tid & 15;

    // ---- phase 1: 8 diagonal blocks, cooperative, sequential ----
    for (int bb = 0; bb < 8; bb++) {
        const int b = cta * 8 + bb;
        float acc = 0.f;
        for (int k0 = 0; k0 < DIM; k0 += 256) {
            for (int t = tid; t < 16 * 256; t += 256) {
                int r = t >> 8, c = t & 255;
                so[r * 257 + c] = O[(size_t)(b * 16 + r) * DIM + k0 + c];
                sp[r * 257 + c] = P[(size_t)(b * 16 + r) * DIM + k0 + c];
            }
            __syncthreads();
#pragma unroll 8
            for (int k = 0; k < 256; k++) acc += so[ti * 257 + k] * sp[tj * 257 + k];
            __syncthreads();
        }
        blk8[bb * 256 + tid] = acc * SCALE;
    }
    __syncthreads();

    // ---- phase 2: 8 concurrent warp-JVs ----
    const int w    = tid >> 5;       // batch within CTA
    const int lane = tid & 31;
    const int b    = cta * 8 + w;
    float* blk = &blk8[w * 256];
    float* uS  = &su [w * 17];
    int*   pS  = &spp[w * 17];
    int*   wS  = &swy[w * 17];

    if (lane < 17) { uS[lane] = 0.f; pS[lane] = 0; }
    float v = 0.f;                 // lane<16: potential of column lane+1
    __syncwarp();

    for (int ii = 1; ii <= 16; ii++) {
        if (lane == 0) pS[0] = ii;
        float minv = 1e30f;
        int   wayr = 0;
        unsigned used = 0u;
        int j0 = 0;
        __syncwarp();

        for (int guard = 0; guard <= 16; guard++) {
            used |= (1u << j0);
            const int i0  = pS[j0];
            const float ui0 = uS[i0];

            bool act = (lane < 16) && !((used >> (lane + 1)) & 1u);
            if (act) {
                float cur = -blk[(i0 - 1) * 16 + lane] - ui0 - v;
                if (cur < minv) { minv = cur; wayr = j0; }
            }
            unsigned ou = act ? ordf(minv) : 0xFFFFFFFFu;
            unsigned mn = __reduce_min_sync(0xffffffffu, ou);
            unsigned bl = __ballot_sync(0xffffffffu, ou == mn);
            int   jm = __ffs(bl);          // winner lane + 1 == column index
            float d  = unordf(mn);

            if (lane < 16) {
                if ((used >> (lane + 1)) & 1u) { v -= d; uS[pS[lane + 1]] += d; }
                else                           { minv -= d; }
            } else if (lane == 16) {
                uS[pS[0]] += d;            // virtual column 0 always used
            }
            __syncwarp();
            j0 = jm;
            if (pS[j0] == 0) break;
        }

        if (lane < 16) wS[lane + 1] = wayr;
        __syncwarp();
        if (lane == 0) {
            int jj = j0;
            while (jj) { int j1 = wS[jj]; pS[jj] = pS[j1]; jj = j1; }
        }
        __syncwarp();
    }

    if (lane < 16) {
        const int row = pS[lane + 1] - 1;   // row matched to column lane
        g_matched[b * 16 + row] = blk[row * 16 + lane];
    }
}

// ---------------------------------------------------------------------------
// Kernel 1: fused diag/JV (first, 32 CTAs) + GEMM.
// ---------------------------------------------------------------------------
__global__ __launch_bounds__(256) void fused_kernel(
    const float* __restrict__ O, const float* __restrict__ P)
{
    extern __shared__ __align__(16) uint8_t dynsmem[];
    if (blockIdx.x < DIAG_CTAS) diag_jv_path(O, P, blockIdx.x, dynsmem);
    else                        gemm_path(dynsmem, blockIdx.x - DIAG_CTAS);
}

// ---------------------------------------------------------------------------
// Kernel 2: per-row loss + fused deterministic mean (last-block sum).
// LSE_nat(r) = ln2 * (M2 + log2(sum_t s_t * 2^(m_t - M2)))
// ---------------------------------------------------------------------------
__global__ __launch_bounds__(128) void finalize_kernel(float* __restrict__ out)
{
    __shared__ float red[128];
    __shared__ unsigned lastf;
    const int row = blockIdx.x * 128 + threadIdx.x;
    float M = -1e30f;
#pragma unroll 8
    for (int t = 0; t < NTILE; t++) M = fmaxf(M, g_pmax[t * NROWS + row]);
    float S = 0.f;
#pragma unroll 8
    for (int t = 0; t < NTILE; t++)
        S += g_psum[t * NROWS + row] * ex2f(g_pmax[t * NROWS + row] - M);
    red[threadIdx.x] = LN2f * (M + lg2f(S)) - g_matched[row];
    __syncthreads();
    for (int s = 64; s; s >>= 1) {
        if (threadIdx.x < s) red[threadIdx.x] += red[threadIdx.x + s];
        __syncthreads();
    }
    if (threadIdx.x == 0) {
        g_partial[blockIdx.x] = red[0];
        __threadfence();
        lastf = (atomicAdd(&g_done, 1u) == (NROWS / 128 - 1));
    }
    __syncthreads();
    if (lastf && threadIdx.x == 0) {
        float s = 0.f;
#pragma unroll
        for (int i = 0; i < NROWS / 128; i++) s += g_partial[i];
        out[0] = s * (1.0f / (float)NROWS);
        g_done = 0;                 // reset for next graph replay
    }
}

// ---------------------------------------------------------------------------
extern "C" void kernel_launch(void* const* d_in, const int* in_sizes, int n_in,
                              void* d_out, int out_size)
{
    const float* O  = (const float*)d_in[0];
    const float* P  = (const float*)d_in[1];
    const float* Ng = (const float*)d_in[2];
    float* out = (float*)d_out;

    static int attr_set = 0;
    if (!attr_set) {
        cudaFuncSetAttribute(fused_kernel,
                             cudaFuncAttributeMaxDynamicSharedMemorySize, SMEM_DYN);
        attr_set = 1;
    }

    convert_kernel<<<2048, 256>>>((const float4*)O, (const float4*)P,
                                  (const float4*)Ng);
    fused_kernel<<<TOTAL_CTAS, 256, SMEM_DYN>>>(O, P);
    finalize_kernel<<<NROWS / 128, 128>>>(out);
}